// round 14
// baseline (speedup 1.0000x reference)
#include <cuda_runtime.h>
#include <cuda_fp16.h>
#include <cstdint>

#define DD   768
#define TT   1024
#define BBATCH 4
#define MM   4096          // B*T
#define HH   6
#define HSZ  128
#define FFD  3072
#define VV   32000
#define LL   6

// ======================= helpers =======================
static __device__ __forceinline__ uint32_t smem_u32(const void* p) {
    uint32_t a;
    asm("{ .reg .u64 t; cvta.to.shared.u64 t, %1; cvt.u32.u64 %0, t; }"
        : "=r"(a) : "l"(p));
    return a;
}

static __device__ __forceinline__ void cp_async16(uint32_t dst_smem, const void* src) {
    asm volatile("cp.async.cg.shared.global [%0], [%1], 16;"
                 :: "r"(dst_smem), "l"(src) : "memory");
}

static __device__ __forceinline__ void mma_f16(float* d, const uint32_t* a,
                                               const uint32_t* b) {
    asm volatile(
        "mma.sync.aligned.m16n8k16.row.col.f32.f16.f16.f32 "
        "{%0,%1,%2,%3}, {%4,%5,%6,%7}, {%8,%9}, {%0,%1,%2,%3};"
        : "+f"(d[0]), "+f"(d[1]), "+f"(d[2]), "+f"(d[3])
        : "r"(a[0]), "r"(a[1]), "r"(a[2]), "r"(a[3]), "r"(b[0]), "r"(b[1]));
}

#define LDSM_X4(R0, R1, R2, R3, ADDR) \
    asm volatile("ldmatrix.sync.aligned.m8n8.x4.shared.b16 {%0,%1,%2,%3}, [%4];" \
                 : "=r"(R0), "=r"(R1), "=r"(R2), "=r"(R3) : "r"(ADDR))

static __device__ __forceinline__ void f16split(float a, __half& hi, __half& lo) {
    hi = __float2half_rn(a);
    lo = __float2half_rn(a - __half2float(hi));
}

static __device__ __forceinline__ uint32_t pack_h2(__half a, __half b) {
    __half2 h = __halves2half2(a, b);
    return *(uint32_t*)&h;
}

static __device__ __forceinline__ void split_store_h2(__half* oh, __half* ol,
                                                      size_t off, float a, float b) {
    __half h0, h1, l0, l1;
    f16split(a, h0, l0);
    f16split(b, h1, l1);
    *(__half2*)(oh + off) = __halves2half2(h0, h1);
    *(__half2*)(ol + off) = __halves2half2(l0, l1);
}

// ======================= scratch (device globals) =======================
__device__ float g_x[MM * DD];

__device__ __half g_h_hi[MM * DD];
__device__ __half g_h_lo[MM * DD];
__device__ __half g_att_hi[MM * DD];
__device__ __half g_att_lo[MM * DD];
__device__ __half g_ff_hi[MM * FFD];
__device__ __half g_ff_lo[MM * FFD];
__device__ __half g_x_hi[MM * DD];
__device__ __half g_x_lo[MM * DD];

__device__ __half g_qkvh[3 * 24 * TT * HSZ];
__device__ __half g_qkvl[3 * 24 * TT * HSZ];

__device__ __half g_wqkvT_hi[LL * 3 * DD * DD];
__device__ __half g_wqkvT_lo[LL * 3 * DD * DD];
__device__ __half g_woT_hi[LL * DD * DD];
__device__ __half g_woT_lo[LL * DD * DD];
__device__ __half g_w1T_hi[LL * FFD * DD];
__device__ __half g_w1T_lo[LL * FFD * DD];
__device__ __half g_w2T_hi[LL * DD * FFD];
__device__ __half g_w2T_lo[LL * DD * FFD];
__device__ __half g_wlmT_hi[(size_t)VV * DD];
__device__ __half g_wlmT_lo[(size_t)VV * DD];

// ======================= weight prep =======================
__global__ void prep_qkvT_k(const float* __restrict__ wq,
                            const float* __restrict__ wk,
                            const float* __restrict__ wv) {
    int i = blockIdx.x * blockDim.x + threadIdx.x;
    const int total = LL * 3 * DD * DD;
    if (i >= total) return;
    int d = i % DD;
    int n = (i / DD) % (3 * DD);
    int l = i / (DD * 3 * DD);
    int sel = n / DD;
    int h = (n % DD) / HSZ;
    int e = n % HSZ;
    size_t src = (((size_t)l * HH + h) * DD + d) * HSZ + e;
    float v = (sel == 0) ? wq[src] : (sel == 1) ? wk[src] : wv[src];
    __half hi, lo;
    f16split(v, hi, lo);
    g_wqkvT_hi[i] = hi;
    g_wqkvT_lo[i] = lo;
}

__global__ void tsplit_k(const float* __restrict__ in,
                         __half* __restrict__ oh, __half* __restrict__ ol,
                         int K, int N) {
    __shared__ float tile[32][33];
    size_t zofs = (size_t)blockIdx.z * K * N;
    in += zofs; oh += zofs; ol += zofs;
    int tx = threadIdx.x, ty = threadIdx.y;
    int x = blockIdx.x * 32 + tx;
    int y0 = blockIdx.y * 32;
    #pragma unroll
    for (int j = 0; j < 32; j += 8)
        tile[ty + j][tx] = in[(size_t)(y0 + ty + j) * N + x];
    __syncthreads();
    #pragma unroll
    for (int j = 0; j < 32; j += 8) {
        float v = tile[tx][ty + j];
        __half hi, lo;
        f16split(v, hi, lo);
        size_t o = (size_t)(blockIdx.x * 32 + ty + j) * K + y0 + tx;
        oh[o] = hi;
        ol[o] = lo;
    }
}

// ======================= embedding =======================
__global__ void embed_k(const int* __restrict__ idx,
                        const float* __restrict__ tok,
                        const float* __restrict__ pos) {
    int i = blockIdx.x * blockDim.x + threadIdx.x;
    if (i >= MM * DD) return;
    int d = i % DD;
    int m = i / DD;
    int t = m % TT;
    g_x[i] = tok[(size_t)idx[m] * DD + d] + pos[t * DD + d];
}

// ======================= layernorm -> split fp16 =======================
__global__ void layernorm_k(const float* __restrict__ x,
                            const float* __restrict__ g,
                            const float* __restrict__ b,
                            __half* __restrict__ oh, __half* __restrict__ ol) {
    int row = blockIdx.x;
    const float* xr = x + (size_t)row * DD;
    int tid = threadIdx.x;  // 256
    float v0 = xr[tid], v1 = xr[tid + 256], v2 = xr[tid + 512];
    float s = v0 + v1 + v2;
    float sq = v0 * v0 + v1 * v1 + v2 * v2;
    __shared__ float shs[8], shq[8];
    #pragma unroll
    for (int o = 16; o; o >>= 1) {
        s  += __shfl_xor_sync(0xffffffffu, s, o);
        sq += __shfl_xor_sync(0xffffffffu, sq, o);
    }
    if ((tid & 31) == 0) { shs[tid >> 5] = s; shq[tid >> 5] = sq; }
    __syncthreads();
    if (tid < 32) {
        s  = (tid < 8) ? shs[tid] : 0.f;
        sq = (tid < 8) ? shq[tid] : 0.f;
        #pragma unroll
        for (int o = 4; o; o >>= 1) {
            s  += __shfl_xor_sync(0xffffffffu, s, o);
            sq += __shfl_xor_sync(0xffffffffu, sq, o);
        }
        if (tid == 0) { shs[0] = s; shq[0] = sq; }
    }
    __syncthreads();
    float mean = shs[0] * (1.f / DD);
    float var  = shq[0] * (1.f / DD) - mean * mean;
    float r = rsqrtf(var + 1e-5f);
    size_t base = (size_t)row * DD;
    #pragma unroll
    for (int u = 0; u < 3; u++) {
        int c = tid + u * 256;
        float v = (u == 0) ? v0 : (u == 1) ? v1 : v2;
        float y = (v - mean) * r * g[c] + b[c];
        __half hi, lo;
        f16split(y, hi, lo);
        oh[base + c] = hi;
        ol[base + c] = lo;
    }
}

// ======================= fp16-split GEMM (BK=32, 2-stage) ==================
// BM = 128 (256 thr, 2 CTAs/SM) or 64 (128 thr, 3 CTAs/SM — for N=768 GEMMs)
// TERMS=3: ah*bh + ah*bl + al*bh ; TERMS=2: ah*bh + ah*bl ; TERMS=1: ah*bh
#define GEMM_SMEM_128 (2 * 40960)
#define GEMM_SMEM_64  (2 * 30720)

template <int EPI, int TERMS, int BM>
__global__ void __launch_bounds__(BM == 64 ? 128 : 256, BM == 64 ? 3 : 2)
gemm2_k(int M, int N, int K,
        const __half* __restrict__ Ahi, const __half* __restrict__ Alo,
        const __half* __restrict__ Bhi, const __half* __restrict__ Blo,
        const float* __restrict__ bias, const float* __restrict__ res,
        float* __restrict__ C,
        __half* __restrict__ outh, __half* __restrict__ outl) {
    constexpr int A_LO   = (BM == 64) ? 5120  : 10240;
    constexpr int B_HI   = (BM == 64) ? 10240 : 20480;
    constexpr int B_PITCH = 10240;
    constexpr int STAGE  = (BM == 64) ? 30720 : 40960;

    extern __shared__ __align__(16) char smem[];
    const uint32_t sb = smem_u32(smem);
    const int tid = threadIdx.x;
    const int wid = tid >> 5, lid = tid & 31;
    const int g = lid >> 2, t4 = lid & 3;
    const int wm = (BM == 64) ? 0 : (wid & 1);
    const int wn = (BM == 64) ? wid : (wid >> 1);
    const int m_off = wm * 64, n_off = wn * 32;

    int bx, by;
    {
        int gid = blockIdx.y * gridDim.x + blockIdx.x;
        int nb = gridDim.x * 4;
        int band = gid / nb;
        int rem = gid % nb;
        by = band * 4 + (rem & 3);
        bx = rem >> 2;
    }
    const int row0 = by * BM, col0 = bx * 128;
    const __half* src[4] = { Ahi + (size_t)row0 * K, Alo + (size_t)row0 * K,
                             Bhi + (size_t)col0 * K, Blo + (size_t)col0 * K };

    const int row_off = lid & 15;
    const int half16  = (lid >> 4) * 16;
    const uint32_t aBase = sb + (m_off + row_off) * 80 + half16;
    const uint32_t bBase = sb + B_HI + (n_off + row_off) * 80 + half16;

    const int r0 = tid >> 2;
    const int c8 = (tid & 3) * 8;
    const int cB = (tid & 3) * 16;

    float acc[4][4][4];
    #pragma unroll
    for (int i = 0; i < 4; i++)
        #pragma unroll
        for (int j = 0; j < 4; j++)
            #pragma unroll
            for (int q = 0; q < 4; q++) acc[i][j][q] = 0.f;

    const int KT = K >> 5;

    auto issue_stage = [&](uint32_t base, int tk) {
        if (BM == 64) {
            #pragma unroll
            for (int mat = 0; mat < 2; mat++) {
                if (TERMS <= 2 && mat == 1) continue;
                const __half* s = src[mat];
                cp_async16(base + mat * A_LO + r0 * 80 + cB,
                           s + (size_t)r0 * K + tk + c8);
                cp_async16(base + mat * A_LO + (r0 + 32) * 80 + cB,
                           s + (size_t)(r0 + 32) * K + tk + c8);
            }
            #pragma unroll
            for (int mat = 0; mat < 2; mat++) {
                if (TERMS == 1 && mat == 1) continue;
                const __half* s = src[2 + mat];
                #pragma unroll
                for (int rr = 0; rr < 4; rr++)
                    cp_async16(base + B_HI + mat * B_PITCH + (r0 + rr * 32) * 80 + cB,
                               s + (size_t)(r0 + rr * 32) * K + tk + c8);
            }
        } else {
            #pragma unroll
            for (int mat = 0; mat < 4; mat++) {
                if (TERMS <= 2 && mat == 1) continue;
                if (TERMS == 1 && mat == 3) continue;
                const __half* s = src[mat];
                uint32_t mb = base + ((mat < 2) ? mat * A_LO : B_HI + (mat - 2) * B_PITCH);
                cp_async16(mb + r0 * 80 + cB, s + (size_t)r0 * K + tk + c8);
                cp_async16(mb + (r0 + 64) * 80 + cB,
                           s + (size_t)(r0 + 64) * K + tk + c8);
            }
        }
        asm volatile("cp.async.commit_group;" ::: "memory");
    };

    issue_stage(sb, 0);

    for (int t = 0; t < KT; t++) {
        const int cur = t & 1;
        asm volatile("cp.async.wait_group 0;" ::: "memory");
        __syncthreads();
        if (t + 1 < KT)
            issue_stage(sb + (cur ^ 1) * STAGE, (t + 1) * 32);

        const uint32_t aA = aBase + cur * STAGE;
        const uint32_t bA = bBase + cur * STAGE;
        #pragma unroll
        for (int kb = 0; kb < 2; kb++) {
            uint32_t bh[4][2], bl[4][2];
            #pragma unroll
            for (int jp = 0; jp < 2; jp++) {
                LDSM_X4(bh[2 * jp][0], bh[2 * jp + 1][0], bh[2 * jp][1], bh[2 * jp + 1][1],
                        bA + jp * 1280 + kb * 32);
                if (TERMS >= 2)
                    LDSM_X4(bl[2 * jp][0], bl[2 * jp + 1][0], bl[2 * jp][1], bl[2 * jp + 1][1],
                            bA + B_PITCH + jp * 1280 + kb * 32);
            }
            #pragma unroll
            for (int i = 0; i < 4; i++) {
                uint32_t ah[4], al[4];
                LDSM_X4(ah[0], ah[1], ah[2], ah[3], aA + i * 1280 + kb * 32);
                if (TERMS == 3)
                    LDSM_X4(al[0], al[1], al[2], al[3],
                            aA + A_LO + i * 1280 + kb * 32);
                #pragma unroll
                for (int j = 0; j < 4; j++)
                    mma_f16(acc[i][j], ah, bh[j]);
                if (TERMS >= 2) {
                    #pragma unroll
                    for (int j = 0; j < 4; j++)
                        mma_f16(acc[i][j], ah, bl[j]);
                }
                if (TERMS == 3) {
                    #pragma unroll
                    for (int j = 0; j < 4; j++)
                        mma_f16(acc[i][j], al, bh[j]);
                }
            }
        }
    }

    // ---- epilogue ----
    #pragma unroll
    for (int i = 0; i < 4; i++) {
        int m0 = row0 + m_off + i * 16 + g;
        #pragma unroll
        for (int j = 0; j < 4; j++) {
            int n0 = col0 + n_off + j * 8 + t4 * 2;
            float v0 = acc[i][j][0], v1 = acc[i][j][1];
            float v2 = acc[i][j][2], v3 = acc[i][j][3];
            if (EPI == 4) {
                #pragma unroll
                for (int q = 0; q < 4; q++) {
                    int m = m0 + (q >> 1) * 8;
                    int n = n0 + (q & 1);
                    float v = (q == 0) ? v0 : (q == 1) ? v1 : (q == 2) ? v2 : v3;
                    int sel = n / DD;
                    int h = (n % DD) >> 7;
                    int e = n & 127;
                    int b = m >> 10;
                    int tt = m & 1023;
                    int bh6 = b * HH + h;
                    size_t o;
                    if (sel < 2) o = ((size_t)(sel * 24 + bh6) << 17) + tt * 128 + e;
                    else         o = ((size_t)(48 + bh6) << 17) + (size_t)e * 1024 + tt;
                    __half hi, lo;
                    f16split(v, hi, lo);
                    outh[o] = hi;
                    outl[o] = lo;
                }
                continue;
            }
            {
                float b0 = bias[n0], b1 = bias[n0 + 1];
                v0 += b0; v1 += b1; v2 += b0; v3 += b1;
            }
            if (EPI == 2) {
                v0 = fmaxf(v0, 0.f); v1 = fmaxf(v1, 0.f);
                v2 = fmaxf(v2, 0.f); v3 = fmaxf(v3, 0.f);
            }
            if (EPI == 3 || EPI == 5) {
                const float* r0p = res + (size_t)m0 * N + n0;
                const float* r1p = res + (size_t)(m0 + 8) * N + n0;
                v0 += r0p[0]; v1 += r0p[1]; v2 += r1p[0]; v3 += r1p[1];
            }
            if (EPI == 1 || EPI == 3 || EPI == 5) {
                *(float2*)(C + (size_t)m0 * N + n0)       = make_float2(v0, v1);
                *(float2*)(C + (size_t)(m0 + 8) * N + n0) = make_float2(v2, v3);
            }
            if (EPI == 2 || EPI == 5) {
                split_store_h2(outh, outl, (size_t)m0 * N + n0, v0, v1);
                split_store_h2(outh, outl, (size_t)(m0 + 8) * N + n0, v2, v3);
            }
        }
    }
}

// ======================= LM head GEMM: BM=128, BN=256, TERMS=1 =============
// Balanced LDS:MMA (8:32 per kb). 1 CTA/SM (acc 128 regs/thread).
// smem/stage: Ahi[128*80] + Bhi[256*80] = 30720 ; 2 stages.
#define LM_STAGE 30720
#define LM_SMEM  (2 * LM_STAGE)

__global__ void __launch_bounds__(256, 1)
lmhead_k(int M, int N, int K,
         const __half* __restrict__ Ahi,
         const __half* __restrict__ Bhi,
         const float* __restrict__ bias,
         float* __restrict__ C) {
    extern __shared__ __align__(16) char smem[];
    const uint32_t sb = smem_u32(smem);
    const int tid = threadIdx.x;
    const int wid = tid >> 5, lid = tid & 31;
    const int g = lid >> 2, t4 = lid & 3;
    const int wm = wid & 1, wn = wid >> 1;     // 2(m) x 4(n), each m64 x n64
    const int m_off = wm * 64, n_off = wn * 64;

    // band-4 swizzle (gridDim.x = N/256 = 125, gridDim.y = 32; 8 bands)
    int bx, by;
    {
        int gid = blockIdx.y * gridDim.x + blockIdx.x;
        int nb = gridDim.x * 4;
        int band = gid / nb;
        int rem = gid % nb;
        by = band * 4 + (rem & 3);
        bx = rem >> 2;
    }
    const int row0 = by * 128, col0 = bx * 256;
    const __half* Ag = Ahi + (size_t)row0 * K;
    const __half* Bg = Bhi + (size_t)col0 * K;

    const int row_off = lid & 15;
    const int half16  = (lid >> 4) * 16;
    const uint32_t aBase = sb + (m_off + row_off) * 80 + half16;
    const uint32_t bBase = sb + 10240 + (n_off + row_off) * 80 + half16;

    const int r0 = tid >> 2;           // 0..63
    const int c8 = (tid & 3) * 8;
    const int cB = (tid & 3) * 16;

    float acc[4][8][4];
    #pragma unroll
    for (int i = 0; i < 4; i++)
        #pragma unroll
        for (int j = 0; j < 8; j++)
            #pragma unroll
            for (int q = 0; q < 4; q++) acc[i][j][q] = 0.f;

    const int KT = K >> 5;             // 24

    auto issue_stage = [&](uint32_t base, int tk) {
        // A: rows r0, r0+64 (128 rows)
        cp_async16(base + r0 * 80 + cB, Ag + (size_t)r0 * K + tk + c8);
        cp_async16(base + (r0 + 64) * 80 + cB,
                   Ag + (size_t)(r0 + 64) * K + tk + c8);
        // B: rows r0 + {0,64,128,192} (256 rows)
        #pragma unroll
        for (int rr = 0; rr < 4; rr++)
            cp_async16(base + 10240 + (r0 + rr * 64) * 80 + cB,
                       Bg + (size_t)(r0 + rr * 64) * K + tk + c8);
        asm volatile("cp.async.commit_group;" ::: "memory");
    };

    issue_stage(sb, 0);

    for (int t = 0; t < KT; t++) {
        const int cur = t & 1;
        asm volatile("cp.async.wait_group 0;" ::: "memory");
        __syncthreads();
        if (t + 1 < KT)
            issue_stage(sb + (cur ^ 1) * LM_STAGE, (t + 1) * 32);

        const uint32_t aA = aBase + cur * LM_STAGE;
        const uint32_t bA = bBase + cur * LM_STAGE;
        #pragma unroll
        for (int kb = 0; kb < 2; kb++) {
            uint32_t bh[8][2];
            #pragma unroll
            for (int jp = 0; jp < 4; jp++)
                LDSM_X4(bh[2 * jp][0], bh[2 * jp + 1][0], bh[2 * jp][1], bh[2 * jp + 1][1],
                        bA + jp * 1280 + kb * 32);
            #pragma unroll
            for (int i = 0; i < 4; i++) {
                uint32_t ah[4];
                LDSM_X4(ah[0], ah[1], ah[2], ah[3], aA + i * 1280 + kb * 32);
                #pragma unroll
                for (int j = 0; j < 8; j++)
                    mma_f16(acc[i][j], ah, bh[j]);
            }
        }
    }

    // ---- epilogue: bias + fp32 store ----
    #pragma unroll
    for (int i = 0; i < 4; i++) {
        int m0 = row0 + m_off + i * 16 + g;
        #pragma unroll
        for (int j = 0; j < 8; j++) {
            int n0 = col0 + n_off + j * 8 + t4 * 2;
            float b0 = bias[n0], b1 = bias[n0 + 1];
            float v0 = acc[i][j][0] + b0, v1 = acc[i][j][1] + b1;
            float v2 = acc[i][j][2] + b0, v3 = acc[i][j][3] + b1;
            *(float2*)(C + (size_t)m0 * N + n0)       = make_float2(v0, v1);
            *(float2*)(C + (size_t)(m0 + 8) * N + n0) = make_float2(v2, v3);
        }
    }
}

// ======================= fused flash attention =======================
#define AQ_H 0
#define AQ_L 17408
#define AK_H 34816
#define AK_L 52224
#define AV_H 69632
#define AV_L 88064
#define ATT_SMEM 106496

__global__ void __launch_bounds__(128)
flash_attn_k(const __half* __restrict__ qkvh, const __half* __restrict__ qkvl,
             __half* __restrict__ atth, __half* __restrict__ attl) {
    extern __shared__ __align__(16) char smem[];
    const uint32_t sb = smem_u32(smem);
    const int bh = blockIdx.y;
    const int qt = 15 - blockIdx.x;
    const int tid = threadIdx.x;
    const int wid = tid >> 5, lid = tid & 31;
    const int g = lid >> 2, t4 = lid & 3;
    const int row_off = lid & 15;
    const int half16 = (lid >> 4) * 16;

    const __half* qh = qkvh + ((size_t)bh << 17) + qt * 64 * 128;
    const __half* ql = qkvl + ((size_t)bh << 17) + qt * 64 * 128;
    #pragma unroll
    for (int it = 0; it < 8; it++) {
        int id = tid + it * 128;
        int r = id >> 4, cb = id & 15;
        cp_async16(sb + AQ_H + r * 272 + cb * 16, qh + r * 128 + cb * 8);
        cp_async16(sb + AQ_L + r * 272 + cb * 16, ql + r * 128 + cb * 8);
    }
    asm volatile("cp.async.commit_group;" ::: "memory");

    float S[8][4];
    float Oa[16][4];
    #pragma unroll
    for (int nb = 0; nb < 16; nb++)
        #pragma unroll
        for (int q = 0; q < 4; q++) Oa[nb][q] = 0.f;
    float m0 = -1e30f, m1 = -1e30f, l0 = 0.f, l1 = 0.f;
    const float scale = 0.08838834764831845f;

    const __half* kbh = qkvh + ((size_t)(24 + bh) << 17);
    const __half* kbl = qkvl + ((size_t)(24 + bh) << 17);
    const __half* vbh = qkvh + ((size_t)(48 + bh) << 17);
    const __half* vbl = qkvl + ((size_t)(48 + bh) << 17);

    for (int kt = 0; kt <= qt; kt++) {
        const __half* kh = kbh + kt * 64 * 128;
        const __half* kl = kbl + kt * 64 * 128;
        #pragma unroll
        for (int it = 0; it < 8; it++) {
            int id = tid + it * 128;
            int r = id >> 4, cb = id & 15;
            cp_async16(sb + AK_H + r * 272 + cb * 16, kh + r * 128 + cb * 8);
            cp_async16(sb + AK_L + r * 272 + cb * 16, kl + r * 128 + cb * 8);
        }
        #pragma unroll
        for (int it = 0; it < 8; it++) {
            int id = tid + it * 128;
            int e = id >> 3, cb = id & 7;
            cp_async16(sb + AV_H + e * 144 + cb * 16,
                       vbh + (size_t)e * 1024 + kt * 64 + cb * 8);
            cp_async16(sb + AV_L + e * 144 + cb * 16,
                       vbl + (size_t)e * 1024 + kt * 64 + cb * 8);
        }
        asm volatile("cp.async.commit_group;" ::: "memory");
        asm volatile("cp.async.wait_group 0;" ::: "memory");
        __syncthreads();

        #pragma unroll
        for (int j = 0; j < 8; j++)
            #pragma unroll
            for (int q = 0; q < 4; q++) S[j][q] = 0.f;
        #pragma unroll
        for (int kb = 0; kb < 8; kb++) {
            uint32_t ah[4], al[4];
            uint32_t qAddr = sb + AQ_H + (wid * 16 + row_off) * 272 + kb * 32 + half16;
            LDSM_X4(ah[0], ah[1], ah[2], ah[3], qAddr);
            LDSM_X4(al[0], al[1], al[2], al[3], qAddr + (AQ_L - AQ_H));
            #pragma unroll
            for (int np = 0; np < 4; np++) {
                uint32_t bh0[2], bh1[2], bl0[2], bl1[2];
                uint32_t kAddr = sb + AK_H + (np * 16 + row_off) * 272 + kb * 32 + half16;
                LDSM_X4(bh0[0], bh1[0], bh0[1], bh1[1], kAddr);
                LDSM_X4(bl0[0], bl1[0], bl0[1], bl1[1], kAddr + (AK_L - AK_H));
                mma_f16(S[2 * np],     ah, bh0);
                mma_f16(S[2 * np + 1], ah, bh1);
                mma_f16(S[2 * np],     ah, bl0);
                mma_f16(S[2 * np + 1], ah, bl1);
                mma_f16(S[2 * np],     al, bh0);
                mma_f16(S[2 * np + 1], al, bh1);
            }
        }

        float mx0 = -1e30f, mx1 = -1e30f;
        #pragma unroll
        for (int j = 0; j < 8; j++) {
            #pragma unroll
            for (int q = 0; q < 4; q++) {
                float sv = S[j][q] * scale;
                if (kt == qt) {
                    int col = j * 8 + t4 * 2 + (q & 1);
                    int row = wid * 16 + g + (q >> 1) * 8;
                    if (col > row) sv = -1e30f;
                }
                S[j][q] = sv;
                if (q < 2) mx0 = fmaxf(mx0, sv);
                else       mx1 = fmaxf(mx1, sv);
            }
        }
        mx0 = fmaxf(mx0, __shfl_xor_sync(0xffffffffu, mx0, 1));
        mx0 = fmaxf(mx0, __shfl_xor_sync(0xffffffffu, mx0, 2));
        mx1 = fmaxf(mx1, __shfl_xor_sync(0xffffffffu, mx1, 1));
        mx1 = fmaxf(mx1, __shfl_xor_sync(0xffffffffu, mx1, 2));
        float mn0 = fmaxf(m0, mx0), mn1 = fmaxf(m1, mx1);
        float alpha0 = __expf(m0 - mn0), alpha1 = __expf(m1 - mn1);
        float sum0 = 0.f, sum1 = 0.f;
        #pragma unroll
        for (int j = 0; j < 8; j++) {
            float p0 = __expf(S[j][0] - mn0);
            float p1 = __expf(S[j][1] - mn0);
            float p2 = __expf(S[j][2] - mn1);
            float p3 = __expf(S[j][3] - mn1);
            S[j][0] = p0; S[j][1] = p1; S[j][2] = p2; S[j][3] = p3;
            sum0 += p0 + p1; sum1 += p2 + p3;
        }
        sum0 += __shfl_xor_sync(0xffffffffu, sum0, 1);
        sum0 += __shfl_xor_sync(0xffffffffu, sum0, 2);
        sum1 += __shfl_xor_sync(0xffffffffu, sum1, 1);
        sum1 += __shfl_xor_sync(0xffffffffu, sum1, 2);
        l0 = l0 * alpha0 + sum0;
        l1 = l1 * alpha1 + sum1;
        m0 = mn0; m1 = mn1;
        #pragma unroll
        for (int nb = 0; nb < 16; nb++) {
            Oa[nb][0] *= alpha0; Oa[nb][1] *= alpha0;
            Oa[nb][2] *= alpha1; Oa[nb][3] *= alpha1;
        }

        #pragma unroll
        for (int kb = 0; kb < 4; kb++) {
            int j0 = 2 * kb, j1 = 2 * kb + 1;
            uint32_t pah[4], pal[4];
            {
                __half h0, h1, lo0, lo1;
                f16split(S[j0][0], h0, lo0); f16split(S[j0][1], h1, lo1);
                pah[0] = pack_h2(h0, h1);  pal[0] = pack_h2(lo0, lo1);
                f16split(S[j0][2], h0, lo0); f16split(S[j0][3], h1, lo1);
                pah[1] = pack_h2(h0, h1);  pal[1] = pack_h2(lo0, lo1);
                f16split(S[j1][0], h0, lo0); f16split(S[j1][1], h1, lo1);
                pah[2] = pack_h2(h0, h1);  pal[2] = pack_h2(lo0, lo1);
                f16split(S[j1][2], h0, lo0); f16split(S[j1][3], h1, lo1);
                pah[3] = pack_h2(h0, h1);  pal[3] = pack_h2(lo0, lo1);
            }
            #pragma unroll
            for (int ep = 0; ep < 8; ep++) {
                uint32_t vh0[2], vh1[2], vl0[2], vl1[2];
                uint32_t vAddr = sb + AV_H + (ep * 16 + row_off) * 144 + kb * 32 + half16;
                LDSM_X4(vh0[0], vh1[0], vh0[1], vh1[1], vAddr);
                LDSM_X4(vl0[0], vl1[0], vl0[1], vl1[1], vAddr + (AV_L - AV_H));
                mma_f16(Oa[2 * ep],     pah, vh0);
                mma_f16(Oa[2 * ep + 1], pah, vh1);
                mma_f16(Oa[2 * ep],     pah, vl0);
                mma_f16(Oa[2 * ep + 1], pah, vl1);
                mma_f16(Oa[2 * ep],     pal, vh0);
                mma_f16(Oa[2 * ep + 1], pal, vh1);
            }
        }
        __syncthreads();
    }

    float inv0 = 1.f / l0, inv1 = 1.f / l1;
    int b = bh / HH, h = bh % HH;
    int trow = qt * 64 + wid * 16 + g;
    size_t o0 = ((size_t)(b * TT + trow)) * DD + h * HSZ;
    size_t o1 = ((size_t)(b * TT + trow + 8)) * DD + h * HSZ;
    #pragma unroll
    for (int nb = 0; nb < 16; nb++) {
        int e = nb * 8 + t4 * 2;
        split_store_h2(atth, attl, o0 + e, Oa[nb][0] * inv0, Oa[nb][1] * inv0);
        split_store_h2(atth, attl, o1 + e, Oa[nb][2] * inv1, Oa[nb][3] * inv1);
    }
}

// ======================= host orchestration =======================
extern "C" void kernel_launch(void* const* d_in, const int* in_sizes, int n_in,
                              void* d_out, int out_size) {
    const int*   idx     = (const int*)d_in[0];
    const float* tok_emb = (const float*)d_in[1];
    const float* pos_emb = (const float*)d_in[2];
    const float* wq      = (const float*)d_in[3];
    const float* wk      = (const float*)d_in[4];
    const float* wv      = (const float*)d_in[5];
    const float* wo      = (const float*)d_in[6];
    const float* bo      = (const float*)d_in[7];
    const float* w1      = (const float*)d_in[8];
    const float* b1      = (const float*)d_in[9];
    const float* w2      = (const float*)d_in[10];
    const float* b2      = (const float*)d_in[11];
    const float* g1      = (const float*)d_in[12];
    const float* be1     = (const float*)d_in[13];
    const float* g2      = (const float*)d_in[14];
    const float* be2     = (const float*)d_in[15];
    const float* wlm     = (const float*)d_in[16];
    const float* blm     = (const float*)d_in[17];
    float* out = (float*)d_out;

    float* px;
    __half *ph_h, *ph_l, *patt_h, *patt_l, *pff_h, *pff_l, *px_h, *px_l;
    __half *pqkvh, *pqkvl;
    __half *pqkvT_h, *pqkvT_l, *pwoT_h, *pwoT_l, *pw1T_h, *pw1T_l,
           *pw2T_h, *pw2T_l, *plmT_h, *plmT_l;
    cudaGetSymbolAddress((void**)&px,     g_x);
    cudaGetSymbolAddress((void**)&ph_h,   g_h_hi);
    cudaGetSymbolAddress((void**)&ph_l,   g_h_lo);
    cudaGetSymbolAddress((void**)&patt_h, g_att_hi);
    cudaGetSymbolAddress((void**)&patt_l, g_att_lo);
    cudaGetSymbolAddress((void**)&pff_h,  g_ff_hi);
    cudaGetSymbolAddress((void**)&pff_l,  g_ff_lo);
    cudaGetSymbolAddress((void**)&px_h,   g_x_hi);
    cudaGetSymbolAddress((void**)&px_l,   g_x_lo);
    cudaGetSymbolAddress((void**)&pqkvh,  g_qkvh);
    cudaGetSymbolAddress((void**)&pqkvl,  g_qkvl);
    cudaGetSymbolAddress((void**)&pqkvT_h, g_wqkvT_hi);
    cudaGetSymbolAddress((void**)&pqkvT_l, g_wqkvT_lo);
    cudaGetSymbolAddress((void**)&pwoT_h,  g_woT_hi);
    cudaGetSymbolAddress((void**)&pwoT_l,  g_woT_lo);
    cudaGetSymbolAddress((void**)&pw1T_h,  g_w1T_hi);
    cudaGetSymbolAddress((void**)&pw1T_l,  g_w1T_lo);
    cudaGetSymbolAddress((void**)&pw2T_h,  g_w2T_hi);
    cudaGetSymbolAddress((void**)&pw2T_l,  g_w2T_lo);
    cudaGetSymbolAddress((void**)&plmT_h,  g_wlmT_hi);
    cudaGetSymbolAddress((void**)&plmT_l,  g_wlmT_lo);

    cudaFuncSetAttribute((const void*)gemm2_k<2, 3, 128>, cudaFuncAttributeMaxDynamicSharedMemorySize, GEMM_SMEM_128);
    cudaFuncSetAttribute((const void*)gemm2_k<4, 3, 128>, cudaFuncAttributeMaxDynamicSharedMemorySize, GEMM_SMEM_128);
    cudaFuncSetAttribute((const void*)gemm2_k<3, 3, 64>,  cudaFuncAttributeMaxDynamicSharedMemorySize, GEMM_SMEM_64);
    cudaFuncSetAttribute((const void*)gemm2_k<5, 3, 64>,  cudaFuncAttributeMaxDynamicSharedMemorySize, GEMM_SMEM_64);
    cudaFuncSetAttribute((const void*)lmhead_k, cudaFuncAttributeMaxDynamicSharedMemorySize, LM_SMEM);
    cudaFuncSetAttribute(flash_attn_k, cudaFuncAttributeMaxDynamicSharedMemorySize, ATT_SMEM);

    {
        int total = LL * 3 * DD * DD;
        prep_qkvT_k<<<(total + 255) / 256, 256>>>(wq, wk, wv);
        dim3 blk(32, 8);
        tsplit_k<<<dim3(DD / 32, DD / 32, LL), blk>>>(wo, pwoT_h, pwoT_l, DD, DD);
        tsplit_k<<<dim3(FFD / 32, DD / 32, LL), blk>>>(w1, pw1T_h, pw1T_l, DD, FFD);
        tsplit_k<<<dim3(DD / 32, FFD / 32, LL), blk>>>(w2, pw2T_h, pw2T_l, FFD, DD);
        tsplit_k<<<dim3(VV / 32, DD / 32, 1), blk>>>(wlm, plmT_h, plmT_l, DD, VV);
        embed_k<<<(MM * DD + 255) / 256, 256>>>(idx, tok_emb, pos_emb);
    }

    for (int l = 0; l < LL; l++) {
        layernorm_k<<<MM, 256>>>(px, g1 + l * DD, be1 + l * DD, ph_h, ph_l);
        gemm2_k<4, 3, 128><<<dim3(3 * DD / 128, MM / 128), 256, GEMM_SMEM_128>>>(
            MM, 3 * DD, DD, ph_h, ph_l,
            pqkvT_h + (size_t)l * 3 * DD * DD,
            pqkvT_l + (size_t)l * 3 * DD * DD,
            nullptr, nullptr, nullptr, pqkvh, pqkvl);
        flash_attn_k<<<dim3(16, 24), 128, ATT_SMEM>>>(pqkvh, pqkvl, patt_h, patt_l);
        gemm2_k<3, 3, 64><<<dim3(DD / 128, MM / 64), 128, GEMM_SMEM_64>>>(
            MM, DD, DD, patt_h, patt_l,
            pwoT_h + (size_t)l * DD * DD,
            pwoT_l + (size_t)l * DD * DD,
            bo + l * DD, px, px, nullptr, nullptr);
        layernorm_k<<<MM, 256>>>(px, g2 + l * DD, be2 + l * DD, ph_h, ph_l);
        gemm2_k<2, 3, 128><<<dim3(FFD / 128, MM / 128), 256, GEMM_SMEM_128>>>(
            MM, FFD, DD, ph_h, ph_l,
            pw1T_h + (size_t)l * FFD * DD,
            pw1T_l + (size_t)l * FFD * DD,
            b1 + l * FFD, nullptr, nullptr, pff_h, pff_l);
        if (l < LL - 1) {
            gemm2_k<3, 3, 64><<<dim3(DD / 128, MM / 64), 128, GEMM_SMEM_64>>>(
                MM, DD, FFD, pff_h, pff_l,
                pw2T_h + (size_t)l * DD * FFD,
                pw2T_l + (size_t)l * DD * FFD,
                b2 + l * DD, px, px, nullptr, nullptr);
        } else {
            gemm2_k<5, 3, 64><<<dim3(DD / 128, MM / 64), 128, GEMM_SMEM_64>>>(
                MM, DD, FFD, pff_h, pff_l,
                pw2T_h + (size_t)l * DD * FFD,
                pw2T_l + (size_t)l * DD * FFD,
                b2 + l * DD, px, px, px_h, px_l);
        }
    }

    // LM head: BN=256 balanced 1-term kernel
    lmhead_k<<<dim3(VV / 256, MM / 128), 256, LM_SMEM>>>(
        MM, VV, DD, px_h, plmT_h, blm, out);
}

// round 15
// speedup vs baseline: 1.0162x; 1.0162x over previous
#include <cuda_runtime.h>
#include <cuda_fp16.h>
#include <cstdint>

#define DD   768
#define TT   1024
#define BBATCH 4
#define MM   4096          // B*T
#define HH   6
#define HSZ  128
#define FFD  3072
#define VV   32000
#define LL   6

// ======================= helpers =======================
static __device__ __forceinline__ uint32_t smem_u32(const void* p) {
    uint32_t a;
    asm("{ .reg .u64 t; cvta.to.shared.u64 t, %1; cvt.u32.u64 %0, t; }"
        : "=r"(a) : "l"(p));
    return a;
}

static __device__ __forceinline__ void cp_async16(uint32_t dst_smem, const void* src) {
    asm volatile("cp.async.cg.shared.global [%0], [%1], 16;"
                 :: "r"(dst_smem), "l"(src) : "memory");
}

static __device__ __forceinline__ void mma_f16(float* d, const uint32_t* a,
                                               const uint32_t* b) {
    asm volatile(
        "mma.sync.aligned.m16n8k16.row.col.f32.f16.f16.f32 "
        "{%0,%1,%2,%3}, {%4,%5,%6,%7}, {%8,%9}, {%0,%1,%2,%3};"
        : "+f"(d[0]), "+f"(d[1]), "+f"(d[2]), "+f"(d[3])
        : "r"(a[0]), "r"(a[1]), "r"(a[2]), "r"(a[3]), "r"(b[0]), "r"(b[1]));
}

#define LDSM_X4(R0, R1, R2, R3, ADDR) \
    asm volatile("ldmatrix.sync.aligned.m8n8.x4.shared.b16 {%0,%1,%2,%3}, [%4];" \
                 : "=r"(R0), "=r"(R1), "=r"(R2), "=r"(R3) : "r"(ADDR))

static __device__ __forceinline__ void f16split(float a, __half& hi, __half& lo) {
    hi = __float2half_rn(a);
    lo = __float2half_rn(a - __half2float(hi));
}

static __device__ __forceinline__ uint32_t pack_h2(__half a, __half b) {
    __half2 h = __halves2half2(a, b);
    return *(uint32_t*)&h;
}

static __device__ __forceinline__ void split_store_h2(__half* oh, __half* ol,
                                                      size_t off, float a, float b) {
    __half h0, h1, l0, l1;
    f16split(a, h0, l0);
    f16split(b, h1, l1);
    *(__half2*)(oh + off) = __halves2half2(h0, h1);
    *(__half2*)(ol + off) = __halves2half2(l0, l1);
}

// ======================= scratch (device globals) =======================
__device__ float g_x[MM * DD];

__device__ __half g_h_hi[MM * DD];
__device__ __half g_h_lo[MM * DD];
__device__ __half g_att_hi[MM * DD];
__device__ __half g_att_lo[MM * DD];
__device__ __half g_ff_hi[MM * FFD];
__device__ __half g_ff_lo[MM * FFD];
__device__ __half g_x_hi[MM * DD];
__device__ __half g_x_lo[MM * DD];   // unused with TERMS=1 LM head (kept for layout)

__device__ __half g_qkvh[3 * 24 * TT * HSZ];
__device__ __half g_qkvl[3 * 24 * TT * HSZ];

__device__ __half g_wqkvT_hi[LL * 3 * DD * DD];
__device__ __half g_wqkvT_lo[LL * 3 * DD * DD];
__device__ __half g_woT_hi[LL * DD * DD];
__device__ __half g_woT_lo[LL * DD * DD];
__device__ __half g_w1T_hi[LL * FFD * DD];
__device__ __half g_w1T_lo[LL * FFD * DD];
__device__ __half g_w2T_hi[LL * DD * FFD];
__device__ __half g_w2T_lo[LL * DD * FFD];
__device__ __half g_wlmT_hi[(size_t)VV * DD];

// ======================= weight prep =======================
__global__ void prep_qkvT_k(const float* __restrict__ wq,
                            const float* __restrict__ wk,
                            const float* __restrict__ wv) {
    int i = blockIdx.x * blockDim.x + threadIdx.x;
    const int total = LL * 3 * DD * DD;
    if (i >= total) return;
    int d = i % DD;
    int n = (i / DD) % (3 * DD);
    int l = i / (DD * 3 * DD);
    int sel = n / DD;
    int h = (n % DD) / HSZ;
    int e = n % HSZ;
    size_t src = (((size_t)l * HH + h) * DD + d) * HSZ + e;
    float v = (sel == 0) ? wq[src] : (sel == 1) ? wk[src] : wv[src];
    __half hi, lo;
    f16split(v, hi, lo);
    g_wqkvT_hi[i] = hi;
    g_wqkvT_lo[i] = lo;
}

__global__ void tsplit_k(const float* __restrict__ in,
                         __half* __restrict__ oh, __half* __restrict__ ol,
                         int K, int N) {
    __shared__ float tile[32][33];
    size_t zofs = (size_t)blockIdx.z * K * N;
    in += zofs; oh += zofs; ol += zofs;
    int tx = threadIdx.x, ty = threadIdx.y;
    int x = blockIdx.x * 32 + tx;
    int y0 = blockIdx.y * 32;
    #pragma unroll
    for (int j = 0; j < 32; j += 8)
        tile[ty + j][tx] = in[(size_t)(y0 + ty + j) * N + x];
    __syncthreads();
    #pragma unroll
    for (int j = 0; j < 32; j += 8) {
        float v = tile[tx][ty + j];
        __half hi, lo;
        f16split(v, hi, lo);
        size_t o = (size_t)(blockIdx.x * 32 + ty + j) * K + y0 + tx;
        oh[o] = hi;
        ol[o] = lo;
    }
}

// hi-only transpose (LM-head weights: lo part is dead with TERMS=1)
__global__ void tsplit_hi_k(const float* __restrict__ in,
                            __half* __restrict__ oh, int K, int N) {
    __shared__ float tile[32][33];
    int tx = threadIdx.x, ty = threadIdx.y;
    int x = blockIdx.x * 32 + tx;
    int y0 = blockIdx.y * 32;
    #pragma unroll
    for (int j = 0; j < 32; j += 8)
        tile[ty + j][tx] = in[(size_t)(y0 + ty + j) * N + x];
    __syncthreads();
    #pragma unroll
    for (int j = 0; j < 32; j += 8) {
        float v = tile[tx][ty + j];
        size_t o = (size_t)(blockIdx.x * 32 + ty + j) * K + y0 + tx;
        oh[o] = __float2half_rn(v);
    }
}

// ======================= embedding =======================
__global__ void embed_k(const int* __restrict__ idx,
                        const float* __restrict__ tok,
                        const float* __restrict__ pos) {
    int i = blockIdx.x * blockDim.x + threadIdx.x;
    if (i >= MM * DD) return;
    int d = i % DD;
    int m = i / DD;
    int t = m % TT;
    g_x[i] = tok[(size_t)idx[m] * DD + d] + pos[t * DD + d];
}

// ======================= layernorm -> split fp16 =======================
__global__ void layernorm_k(const float* __restrict__ x,
                            const float* __restrict__ g,
                            const float* __restrict__ b,
                            __half* __restrict__ oh, __half* __restrict__ ol) {
    int row = blockIdx.x;
    const float* xr = x + (size_t)row * DD;
    int tid = threadIdx.x;  // 256
    float v0 = xr[tid], v1 = xr[tid + 256], v2 = xr[tid + 512];
    float s = v0 + v1 + v2;
    float sq = v0 * v0 + v1 * v1 + v2 * v2;
    __shared__ float shs[8], shq[8];
    #pragma unroll
    for (int o = 16; o; o >>= 1) {
        s  += __shfl_xor_sync(0xffffffffu, s, o);
        sq += __shfl_xor_sync(0xffffffffu, sq, o);
    }
    if ((tid & 31) == 0) { shs[tid >> 5] = s; shq[tid >> 5] = sq; }
    __syncthreads();
    if (tid < 32) {
        s  = (tid < 8) ? shs[tid] : 0.f;
        sq = (tid < 8) ? shq[tid] : 0.f;
        #pragma unroll
        for (int o = 4; o; o >>= 1) {
            s  += __shfl_xor_sync(0xffffffffu, s, o);
            sq += __shfl_xor_sync(0xffffffffu, sq, o);
        }
        if (tid == 0) { shs[0] = s; shq[0] = sq; }
    }
    __syncthreads();
    float mean = shs[0] * (1.f / DD);
    float var  = shq[0] * (1.f / DD) - mean * mean;
    float r = rsqrtf(var + 1e-5f);
    size_t base = (size_t)row * DD;
    #pragma unroll
    for (int u = 0; u < 3; u++) {
        int c = tid + u * 256;
        float v = (u == 0) ? v0 : (u == 1) ? v1 : v2;
        float y = (v - mean) * r * g[c] + b[c];
        __half hi, lo;
        f16split(y, hi, lo);
        oh[base + c] = hi;
        ol[base + c] = lo;
    }
}

// ======================= fp16-split GEMM (BK=32, 2-stage) ==================
// BM = 128 (256 thr, 2 CTAs/SM) or 64 (128 thr, 3 CTAs/SM — for N=768 GEMMs)
// TERMS=3: ah*bh + ah*bl + al*bh ; TERMS=2: ah*bh + ah*bl ; TERMS=1: ah*bh
// EPI: 1 bias->C ; 2 bias+relu->split ; 3 bias+res->C ; 4 qkv scatter ;
//      5 bias+res->C + split ; 6 bias+res->C + hi-only split
#define GEMM_SMEM_128 (2 * 40960)
#define GEMM_SMEM_64  (2 * 30720)

template <int EPI, int TERMS, int BM>
__global__ void __launch_bounds__(BM == 64 ? 128 : 256, BM == 64 ? 3 : 2)
gemm2_k(int M, int N, int K,
        const __half* __restrict__ Ahi, const __half* __restrict__ Alo,
        const __half* __restrict__ Bhi, const __half* __restrict__ Blo,
        const float* __restrict__ bias, const float* __restrict__ res,
        float* __restrict__ C,
        __half* __restrict__ outh, __half* __restrict__ outl) {
    constexpr int A_LO   = (BM == 64) ? 5120  : 10240;
    constexpr int B_HI   = (BM == 64) ? 10240 : 20480;
    constexpr int B_PITCH = 10240;
    constexpr int STAGE  = (BM == 64) ? 30720 : 40960;

    extern __shared__ __align__(16) char smem[];
    const uint32_t sb = smem_u32(smem);
    const int tid = threadIdx.x;
    const int wid = tid >> 5, lid = tid & 31;
    const int g = lid >> 2, t4 = lid & 3;
    const int wm = (BM == 64) ? 0 : (wid & 1);
    const int wn = (BM == 64) ? wid : (wid >> 1);
    const int m_off = wm * 64, n_off = wn * 32;

    int bx, by;
    {
        int gid = blockIdx.y * gridDim.x + blockIdx.x;
        int nb = gridDim.x * 4;
        int band = gid / nb;
        int rem = gid % nb;
        by = band * 4 + (rem & 3);
        bx = rem >> 2;
    }
    const int row0 = by * BM, col0 = bx * 128;
    const __half* src[4] = { Ahi + (size_t)row0 * K, Alo + (size_t)row0 * K,
                             Bhi + (size_t)col0 * K, Blo + (size_t)col0 * K };

    const int row_off = lid & 15;
    const int half16  = (lid >> 4) * 16;
    const uint32_t aBase = sb + (m_off + row_off) * 80 + half16;
    const uint32_t bBase = sb + B_HI + (n_off + row_off) * 80 + half16;

    const int r0 = tid >> 2;
    const int c8 = (tid & 3) * 8;
    const int cB = (tid & 3) * 16;

    float acc[4][4][4];
    #pragma unroll
    for (int i = 0; i < 4; i++)
        #pragma unroll
        for (int j = 0; j < 4; j++)
            #pragma unroll
            for (int q = 0; q < 4; q++) acc[i][j][q] = 0.f;

    const int KT = K >> 5;

    auto issue_stage = [&](uint32_t base, int tk) {
        if (BM == 64) {
            #pragma unroll
            for (int mat = 0; mat < 2; mat++) {
                if (TERMS <= 2 && mat == 1) continue;
                const __half* s = src[mat];
                cp_async16(base + mat * A_LO + r0 * 80 + cB,
                           s + (size_t)r0 * K + tk + c8);
                cp_async16(base + mat * A_LO + (r0 + 32) * 80 + cB,
                           s + (size_t)(r0 + 32) * K + tk + c8);
            }
            #pragma unroll
            for (int mat = 0; mat < 2; mat++) {
                if (TERMS == 1 && mat == 1) continue;
                const __half* s = src[2 + mat];
                #pragma unroll
                for (int rr = 0; rr < 4; rr++)
                    cp_async16(base + B_HI + mat * B_PITCH + (r0 + rr * 32) * 80 + cB,
                               s + (size_t)(r0 + rr * 32) * K + tk + c8);
            }
        } else {
            #pragma unroll
            for (int mat = 0; mat < 4; mat++) {
                if (TERMS <= 2 && mat == 1) continue;
                if (TERMS == 1 && mat == 3) continue;
                const __half* s = src[mat];
                uint32_t mb = base + ((mat < 2) ? mat * A_LO : B_HI + (mat - 2) * B_PITCH);
                cp_async16(mb + r0 * 80 + cB, s + (size_t)r0 * K + tk + c8);
                cp_async16(mb + (r0 + 64) * 80 + cB,
                           s + (size_t)(r0 + 64) * K + tk + c8);
            }
        }
        asm volatile("cp.async.commit_group;" ::: "memory");
    };

    issue_stage(sb, 0);

    for (int t = 0; t < KT; t++) {
        const int cur = t & 1;
        asm volatile("cp.async.wait_group 0;" ::: "memory");
        __syncthreads();
        if (t + 1 < KT)
            issue_stage(sb + (cur ^ 1) * STAGE, (t + 1) * 32);

        const uint32_t aA = aBase + cur * STAGE;
        const uint32_t bA = bBase + cur * STAGE;
        #pragma unroll
        for (int kb = 0; kb < 2; kb++) {
            uint32_t bh[4][2], bl[4][2];
            #pragma unroll
            for (int jp = 0; jp < 2; jp++) {
                LDSM_X4(bh[2 * jp][0], bh[2 * jp + 1][0], bh[2 * jp][1], bh[2 * jp + 1][1],
                        bA + jp * 1280 + kb * 32);
                if (TERMS >= 2)
                    LDSM_X4(bl[2 * jp][0], bl[2 * jp + 1][0], bl[2 * jp][1], bl[2 * jp + 1][1],
                            bA + B_PITCH + jp * 1280 + kb * 32);
            }
            #pragma unroll
            for (int i = 0; i < 4; i++) {
                uint32_t ah[4], al[4];
                LDSM_X4(ah[0], ah[1], ah[2], ah[3], aA + i * 1280 + kb * 32);
                if (TERMS == 3)
                    LDSM_X4(al[0], al[1], al[2], al[3],
                            aA + A_LO + i * 1280 + kb * 32);
                #pragma unroll
                for (int j = 0; j < 4; j++)
                    mma_f16(acc[i][j], ah, bh[j]);
                if (TERMS >= 2) {
                    #pragma unroll
                    for (int j = 0; j < 4; j++)
                        mma_f16(acc[i][j], ah, bl[j]);
                }
                if (TERMS == 3) {
                    #pragma unroll
                    for (int j = 0; j < 4; j++)
                        mma_f16(acc[i][j], al, bh[j]);
                }
            }
        }
    }

    // ---- epilogue ----
    #pragma unroll
    for (int i = 0; i < 4; i++) {
        int m0 = row0 + m_off + i * 16 + g;
        #pragma unroll
        for (int j = 0; j < 4; j++) {
            int n0 = col0 + n_off + j * 8 + t4 * 2;
            float v0 = acc[i][j][0], v1 = acc[i][j][1];
            float v2 = acc[i][j][2], v3 = acc[i][j][3];
            if (EPI == 4) {
                #pragma unroll
                for (int q = 0; q < 4; q++) {
                    int m = m0 + (q >> 1) * 8;
                    int n = n0 + (q & 1);
                    float v = (q == 0) ? v0 : (q == 1) ? v1 : (q == 2) ? v2 : v3;
                    int sel = n / DD;
                    int h = (n % DD) >> 7;
                    int e = n & 127;
                    int b = m >> 10;
                    int tt = m & 1023;
                    int bh6 = b * HH + h;
                    size_t o;
                    if (sel < 2) o = ((size_t)(sel * 24 + bh6) << 17) + tt * 128 + e;
                    else         o = ((size_t)(48 + bh6) << 17) + (size_t)e * 1024 + tt;
                    __half hi, lo;
                    f16split(v, hi, lo);
                    outh[o] = hi;
                    outl[o] = lo;
                }
                continue;
            }
            {
                float b0 = bias[n0], b1 = bias[n0 + 1];
                v0 += b0; v1 += b1; v2 += b0; v3 += b1;
            }
            if (EPI == 2) {
                v0 = fmaxf(v0, 0.f); v1 = fmaxf(v1, 0.f);
                v2 = fmaxf(v2, 0.f); v3 = fmaxf(v3, 0.f);
            }
            if (EPI == 3 || EPI == 5 || EPI == 6) {
                const float* r0p = res + (size_t)m0 * N + n0;
                const float* r1p = res + (size_t)(m0 + 8) * N + n0;
                v0 += r0p[0]; v1 += r0p[1]; v2 += r1p[0]; v3 += r1p[1];
            }
            if (EPI == 1 || EPI == 3 || EPI == 5 || EPI == 6) {
                *(float2*)(C + (size_t)m0 * N + n0)       = make_float2(v0, v1);
                *(float2*)(C + (size_t)(m0 + 8) * N + n0) = make_float2(v2, v3);
            }
            if (EPI == 2 || EPI == 5) {
                split_store_h2(outh, outl, (size_t)m0 * N + n0, v0, v1);
                split_store_h2(outh, outl, (size_t)(m0 + 8) * N + n0, v2, v3);
            }
            if (EPI == 6) {  // hi-only (LM-head input; lo is dead with TERMS=1)
                *(__half2*)(outh + (size_t)m0 * N + n0) =
                    __halves2half2(__float2half_rn(v0), __float2half_rn(v1));
                *(__half2*)(outh + (size_t)(m0 + 8) * N + n0) =
                    __halves2half2(__float2half_rn(v2), __float2half_rn(v3));
            }
        }
    }
}

// ======================= fused flash attention =======================
#define AQ_H 0
#define AQ_L 17408
#define AK_H 34816
#define AK_L 52224
#define AV_H 69632
#define AV_L 88064
#define ATT_SMEM 106496

__global__ void __launch_bounds__(128)
flash_attn_k(const __half* __restrict__ qkvh, const __half* __restrict__ qkvl,
             __half* __restrict__ atth, __half* __restrict__ attl) {
    extern __shared__ __align__(16) char smem[];
    const uint32_t sb = smem_u32(smem);
    const int bh = blockIdx.y;
    const int qt = 15 - blockIdx.x;
    const int tid = threadIdx.x;
    const int wid = tid >> 5, lid = tid & 31;
    const int g = lid >> 2, t4 = lid & 3;
    const int row_off = lid & 15;
    const int half16 = (lid >> 4) * 16;

    const __half* qh = qkvh + ((size_t)bh << 17) + qt * 64 * 128;
    const __half* ql = qkvl + ((size_t)bh << 17) + qt * 64 * 128;
    #pragma unroll
    for (int it = 0; it < 8; it++) {
        int id = tid + it * 128;
        int r = id >> 4, cb = id & 15;
        cp_async16(sb + AQ_H + r * 272 + cb * 16, qh + r * 128 + cb * 8);
        cp_async16(sb + AQ_L + r * 272 + cb * 16, ql + r * 128 + cb * 8);
    }
    asm volatile("cp.async.commit_group;" ::: "memory");

    float S[8][4];
    float Oa[16][4];
    #pragma unroll
    for (int nb = 0; nb < 16; nb++)
        #pragma unroll
        for (int q = 0; q < 4; q++) Oa[nb][q] = 0.f;
    float m0 = -1e30f, m1 = -1e30f, l0 = 0.f, l1 = 0.f;
    const float scale = 0.08838834764831845f;

    const __half* kbh = qkvh + ((size_t)(24 + bh) << 17);
    const __half* kbl = qkvl + ((size_t)(24 + bh) << 17);
    const __half* vbh = qkvh + ((size_t)(48 + bh) << 17);
    const __half* vbl = qkvl + ((size_t)(48 + bh) << 17);

    for (int kt = 0; kt <= qt; kt++) {
        const __half* kh = kbh + kt * 64 * 128;
        const __half* kl = kbl + kt * 64 * 128;
        #pragma unroll
        for (int it = 0; it < 8; it++) {
            int id = tid + it * 128;
            int r = id >> 4, cb = id & 15;
            cp_async16(sb + AK_H + r * 272 + cb * 16, kh + r * 128 + cb * 8);
            cp_async16(sb + AK_L + r * 272 + cb * 16, kl + r * 128 + cb * 8);
        }
        #pragma unroll
        for (int it = 0; it < 8; it++) {
            int id = tid + it * 128;
            int e = id >> 3, cb = id & 7;
            cp_async16(sb + AV_H + e * 144 + cb * 16,
                       vbh + (size_t)e * 1024 + kt * 64 + cb * 8);
            cp_async16(sb + AV_L + e * 144 + cb * 16,
                       vbl + (size_t)e * 1024 + kt * 64 + cb * 8);
        }
        asm volatile("cp.async.commit_group;" ::: "memory");
        asm volatile("cp.async.wait_group 0;" ::: "memory");
        __syncthreads();

        #pragma unroll
        for (int j = 0; j < 8; j++)
            #pragma unroll
            for (int q = 0; q < 4; q++) S[j][q] = 0.f;
        #pragma unroll
        for (int kb = 0; kb < 8; kb++) {
            uint32_t ah[4], al[4];
            uint32_t qAddr = sb + AQ_H + (wid * 16 + row_off) * 272 + kb * 32 + half16;
            LDSM_X4(ah[0], ah[1], ah[2], ah[3], qAddr);
            LDSM_X4(al[0], al[1], al[2], al[3], qAddr + (AQ_L - AQ_H));
            #pragma unroll
            for (int np = 0; np < 4; np++) {
                uint32_t bh0[2], bh1[2], bl0[2], bl1[2];
                uint32_t kAddr = sb + AK_H + (np * 16 + row_off) * 272 + kb * 32 + half16;
                LDSM_X4(bh0[0], bh1[0], bh0[1], bh1[1], kAddr);
                LDSM_X4(bl0[0], bl1[0], bl0[1], bl1[1], kAddr + (AK_L - AK_H));
                mma_f16(S[2 * np],     ah, bh0);
                mma_f16(S[2 * np + 1], ah, bh1);
                mma_f16(S[2 * np],     ah, bl0);
                mma_f16(S[2 * np + 1], ah, bl1);
                mma_f16(S[2 * np],     al, bh0);
                mma_f16(S[2 * np + 1], al, bh1);
            }
        }

        float mx0 = -1e30f, mx1 = -1e30f;
        #pragma unroll
        for (int j = 0; j < 8; j++) {
            #pragma unroll
            for (int q = 0; q < 4; q++) {
                float sv = S[j][q] * scale;
                if (kt == qt) {
                    int col = j * 8 + t4 * 2 + (q & 1);
                    int row = wid * 16 + g + (q >> 1) * 8;
                    if (col > row) sv = -1e30f;
                }
                S[j][q] = sv;
                if (q < 2) mx0 = fmaxf(mx0, sv);
                else       mx1 = fmaxf(mx1, sv);
            }
        }
        mx0 = fmaxf(mx0, __shfl_xor_sync(0xffffffffu, mx0, 1));
        mx0 = fmaxf(mx0, __shfl_xor_sync(0xffffffffu, mx0, 2));
        mx1 = fmaxf(mx1, __shfl_xor_sync(0xffffffffu, mx1, 1));
        mx1 = fmaxf(mx1, __shfl_xor_sync(0xffffffffu, mx1, 2));
        float mn0 = fmaxf(m0, mx0), mn1 = fmaxf(m1, mx1);
        float alpha0 = __expf(m0 - mn0), alpha1 = __expf(m1 - mn1);
        float sum0 = 0.f, sum1 = 0.f;
        #pragma unroll
        for (int j = 0; j < 8; j++) {
            float p0 = __expf(S[j][0] - mn0);
            float p1 = __expf(S[j][1] - mn0);
            float p2 = __expf(S[j][2] - mn1);
            float p3 = __expf(S[j][3] - mn1);
            S[j][0] = p0; S[j][1] = p1; S[j][2] = p2; S[j][3] = p3;
            sum0 += p0 + p1; sum1 += p2 + p3;
        }
        sum0 += __shfl_xor_sync(0xffffffffu, sum0, 1);
        sum0 += __shfl_xor_sync(0xffffffffu, sum0, 2);
        sum1 += __shfl_xor_sync(0xffffffffu, sum1, 1);
        sum1 += __shfl_xor_sync(0xffffffffu, sum1, 2);
        l0 = l0 * alpha0 + sum0;
        l1 = l1 * alpha1 + sum1;
        m0 = mn0; m1 = mn1;
        #pragma unroll
        for (int nb = 0; nb < 16; nb++) {
            Oa[nb][0] *= alpha0; Oa[nb][1] *= alpha0;
            Oa[nb][2] *= alpha1; Oa[nb][3] *= alpha1;
        }

        #pragma unroll
        for (int kb = 0; kb < 4; kb++) {
            int j0 = 2 * kb, j1 = 2 * kb + 1;
            uint32_t pah[4], pal[4];
            {
                __half h0, h1, lo0, lo1;
                f16split(S[j0][0], h0, lo0); f16split(S[j0][1], h1, lo1);
                pah[0] = pack_h2(h0, h1);  pal[0] = pack_h2(lo0, lo1);
                f16split(S[j0][2], h0, lo0); f16split(S[j0][3], h1, lo1);
                pah[1] = pack_h2(h0, h1);  pal[1] = pack_h2(lo0, lo1);
                f16split(S[j1][0], h0, lo0); f16split(S[j1][1], h1, lo1);
                pah[2] = pack_h2(h0, h1);  pal[2] = pack_h2(lo0, lo1);
                f16split(S[j1][2], h0, lo0); f16split(S[j1][3], h1, lo1);
                pah[3] = pack_h2(h0, h1);  pal[3] = pack_h2(lo0, lo1);
            }
            #pragma unroll
            for (int ep = 0; ep < 8; ep++) {
                uint32_t vh0[2], vh1[2], vl0[2], vl1[2];
                uint32_t vAddr = sb + AV_H + (ep * 16 + row_off) * 144 + kb * 32 + half16;
                LDSM_X4(vh0[0], vh1[0], vh0[1], vh1[1], vAddr);
                LDSM_X4(vl0[0], vl1[0], vl0[1], vl1[1], vAddr + (AV_L - AV_H));
                mma_f16(Oa[2 * ep],     pah, vh0);
                mma_f16(Oa[2 * ep + 1], pah, vh1);
                mma_f16(Oa[2 * ep],     pah, vl0);
                mma_f16(Oa[2 * ep + 1], pah, vl1);
                mma_f16(Oa[2 * ep],     pal, vh0);
                mma_f16(Oa[2 * ep + 1], pal, vh1);
            }
        }
        __syncthreads();
    }

    float inv0 = 1.f / l0, inv1 = 1.f / l1;
    int b = bh / HH, h = bh % HH;
    int trow = qt * 64 + wid * 16 + g;
    size_t o0 = ((size_t)(b * TT + trow)) * DD + h * HSZ;
    size_t o1 = ((size_t)(b * TT + trow + 8)) * DD + h * HSZ;
    #pragma unroll
    for (int nb = 0; nb < 16; nb++) {
        int e = nb * 8 + t4 * 2;
        split_store_h2(atth, attl, o0 + e, Oa[nb][0] * inv0, Oa[nb][1] * inv0);
        split_store_h2(atth, attl, o1 + e, Oa[nb][2] * inv1, Oa[nb][3] * inv1);
    }
}

// ======================= host orchestration =======================
extern "C" void kernel_launch(void* const* d_in, const int* in_sizes, int n_in,
                              void* d_out, int out_size) {
    const int*   idx     = (const int*)d_in[0];
    const float* tok_emb = (const float*)d_in[1];
    const float* pos_emb = (const float*)d_in[2];
    const float* wq      = (const float*)d_in[3];
    const float* wk      = (const float*)d_in[4];
    const float* wv      = (const float*)d_in[5];
    const float* wo      = (const float*)d_in[6];
    const float* bo      = (const float*)d_in[7];
    const float* w1      = (const float*)d_in[8];
    const float* b1      = (const float*)d_in[9];
    const float* w2      = (const float*)d_in[10];
    const float* b2      = (const float*)d_in[11];
    const float* g1      = (const float*)d_in[12];
    const float* be1     = (const float*)d_in[13];
    const float* g2      = (const float*)d_in[14];
    const float* be2     = (const float*)d_in[15];
    const float* wlm     = (const float*)d_in[16];
    const float* blm     = (const float*)d_in[17];
    float* out = (float*)d_out;

    float* px;
    __half *ph_h, *ph_l, *patt_h, *patt_l, *pff_h, *pff_l, *px_h, *px_l;
    __half *pqkvh, *pqkvl;
    __half *pqkvT_h, *pqkvT_l, *pwoT_h, *pwoT_l, *pw1T_h, *pw1T_l,
           *pw2T_h, *pw2T_l, *plmT_h;
    cudaGetSymbolAddress((void**)&px,     g_x);
    cudaGetSymbolAddress((void**)&ph_h,   g_h_hi);
    cudaGetSymbolAddress((void**)&ph_l,   g_h_lo);
    cudaGetSymbolAddress((void**)&patt_h, g_att_hi);
    cudaGetSymbolAddress((void**)&patt_l, g_att_lo);
    cudaGetSymbolAddress((void**)&pff_h,  g_ff_hi);
    cudaGetSymbolAddress((void**)&pff_l,  g_ff_lo);
    cudaGetSymbolAddress((void**)&px_h,   g_x_hi);
    cudaGetSymbolAddress((void**)&px_l,   g_x_lo);
    cudaGetSymbolAddress((void**)&pqkvh,  g_qkvh);
    cudaGetSymbolAddress((void**)&pqkvl,  g_qkvl);
    cudaGetSymbolAddress((void**)&pqkvT_h, g_wqkvT_hi);
    cudaGetSymbolAddress((void**)&pqkvT_l, g_wqkvT_lo);
    cudaGetSymbolAddress((void**)&pwoT_h,  g_woT_hi);
    cudaGetSymbolAddress((void**)&pwoT_l,  g_woT_lo);
    cudaGetSymbolAddress((void**)&pw1T_h,  g_w1T_hi);
    cudaGetSymbolAddress((void**)&pw1T_l,  g_w1T_lo);
    cudaGetSymbolAddress((void**)&pw2T_h,  g_w2T_hi);
    cudaGetSymbolAddress((void**)&pw2T_l,  g_w2T_lo);
    cudaGetSymbolAddress((void**)&plmT_h,  g_wlmT_hi);

    cudaFuncSetAttribute((const void*)gemm2_k<1, 1, 128>, cudaFuncAttributeMaxDynamicSharedMemorySize, GEMM_SMEM_128);
    cudaFuncSetAttribute((const void*)gemm2_k<2, 3, 128>, cudaFuncAttributeMaxDynamicSharedMemorySize, GEMM_SMEM_128);
    cudaFuncSetAttribute((const void*)gemm2_k<4, 3, 128>, cudaFuncAttributeMaxDynamicSharedMemorySize, GEMM_SMEM_128);
    cudaFuncSetAttribute((const void*)gemm2_k<3, 3, 64>,  cudaFuncAttributeMaxDynamicSharedMemorySize, GEMM_SMEM_64);
    cudaFuncSetAttribute((const void*)gemm2_k<6, 3, 64>,  cudaFuncAttributeMaxDynamicSharedMemorySize, GEMM_SMEM_64);
    cudaFuncSetAttribute(flash_attn_k, cudaFuncAttributeMaxDynamicSharedMemorySize, ATT_SMEM);

    {
        int total = LL * 3 * DD * DD;
        prep_qkvT_k<<<(total + 255) / 256, 256>>>(wq, wk, wv);
        dim3 blk(32, 8);
        tsplit_k<<<dim3(DD / 32, DD / 32, LL), blk>>>(wo, pwoT_h, pwoT_l, DD, DD);
        tsplit_k<<<dim3(FFD / 32, DD / 32, LL), blk>>>(w1, pw1T_h, pw1T_l, DD, FFD);
        tsplit_k<<<dim3(DD / 32, FFD / 32, LL), blk>>>(w2, pw2T_h, pw2T_l, FFD, DD);
        tsplit_hi_k<<<dim3(VV / 32, DD / 32, 1), blk>>>(wlm, plmT_h, DD, VV);
        embed_k<<<(MM * DD + 255) / 256, 256>>>(idx, tok_emb, pos_emb);
    }

    for (int l = 0; l < LL; l++) {
        layernorm_k<<<MM, 256>>>(px, g1 + l * DD, be1 + l * DD, ph_h, ph_l);
        gemm2_k<4, 3, 128><<<dim3(3 * DD / 128, MM / 128), 256, GEMM_SMEM_128>>>(
            MM, 3 * DD, DD, ph_h, ph_l,
            pqkvT_h + (size_t)l * 3 * DD * DD,
            pqkvT_l + (size_t)l * 3 * DD * DD,
            nullptr, nullptr, nullptr, pqkvh, pqkvl);
        flash_attn_k<<<dim3(16, 24), 128, ATT_SMEM>>>(pqkvh, pqkvl, patt_h, patt_l);
        gemm2_k<3, 3, 64><<<dim3(DD / 128, MM / 64), 128, GEMM_SMEM_64>>>(
            MM, DD, DD, patt_h, patt_l,
            pwoT_h + (size_t)l * DD * DD,
            pwoT_l + (size_t)l * DD * DD,
            bo + l * DD, px, px, nullptr, nullptr);
        layernorm_k<<<MM, 256>>>(px, g2 + l * DD, be2 + l * DD, ph_h, ph_l);
        gemm2_k<2, 3, 128><<<dim3(FFD / 128, MM / 128), 256, GEMM_SMEM_128>>>(
            MM, FFD, DD, ph_h, ph_l,
            pw1T_h + (size_t)l * FFD * DD,
            pw1T_l + (size_t)l * FFD * DD,
            b1 + l * FFD, nullptr, nullptr, pff_h, pff_l);
        if (l < LL - 1) {
            gemm2_k<3, 3, 64><<<dim3(DD / 128, MM / 64), 128, GEMM_SMEM_64>>>(
                MM, DD, FFD, pff_h, pff_l,
                pw2T_h + (size_t)l * DD * FFD,
                pw2T_l + (size_t)l * DD * FFD,
                b2 + l * DD, px, px, nullptr, nullptr);
        } else {
            // hi-only split output (LM head is TERMS=1; lo is dead)
            gemm2_k<6, 3, 64><<<dim3(DD / 128, MM / 64), 128, GEMM_SMEM_64>>>(
                MM, DD, FFD, pff_h, pff_l,
                pw2T_h + (size_t)l * DD * FFD,
                pw2T_l + (size_t)l * DD * FFD,
                b2 + l * DD, px, px, px_h, nullptr);
        }
    }

    // LM head (final op): 1-term fp16, BM=128 tile (R13 configuration)
    gemm2_k<1, 1, 128><<<dim3(VV / 128, MM / 128), 256, GEMM_SMEM_128>>>(
        MM, VV, DD, px_h, px_l, plmT_h, nullptr, blm, nullptr, out,
        nullptr, nullptr);
}

// round 16
// speedup vs baseline: 1.0436x; 1.0269x over previous
#include <cuda_runtime.h>
#include <cuda_fp16.h>
#include <cstdint>

#define DD   768
#define TT   1024
#define BBATCH 4
#define MM   4096          // B*T
#define HH   6
#define HSZ  128
#define FFD  3072
#define VV   32000
#define LL   6

// ======================= helpers =======================
static __device__ __forceinline__ uint32_t smem_u32(const void* p) {
    uint32_t a;
    asm("{ .reg .u64 t; cvta.to.shared.u64 t, %1; cvt.u32.u64 %0, t; }"
        : "=r"(a) : "l"(p));
    return a;
}

static __device__ __forceinline__ void cp_async16(uint32_t dst_smem, const void* src) {
    asm volatile("cp.async.cg.shared.global [%0], [%1], 16;"
                 :: "r"(dst_smem), "l"(src) : "memory");
}

static __device__ __forceinline__ void mma_f16(float* d, const uint32_t* a,
                                               const uint32_t* b) {
    asm volatile(
        "mma.sync.aligned.m16n8k16.row.col.f32.f16.f16.f32 "
        "{%0,%1,%2,%3}, {%4,%5,%6,%7}, {%8,%9}, {%0,%1,%2,%3};"
        : "+f"(d[0]), "+f"(d[1]), "+f"(d[2]), "+f"(d[3])
        : "r"(a[0]), "r"(a[1]), "r"(a[2]), "r"(a[3]), "r"(b[0]), "r"(b[1]));
}

#define LDSM_X4(R0, R1, R2, R3, ADDR) \
    asm volatile("ldmatrix.sync.aligned.m8n8.x4.shared.b16 {%0,%1,%2,%3}, [%4];" \
                 : "=r"(R0), "=r"(R1), "=r"(R2), "=r"(R3) : "r"(ADDR))

static __device__ __forceinline__ void f16split(float a, __half& hi, __half& lo) {
    hi = __float2half_rn(a);
    lo = __float2half_rn(a - __half2float(hi));
}

static __device__ __forceinline__ uint32_t pack_h2(__half a, __half b) {
    __half2 h = __halves2half2(a, b);
    return *(uint32_t*)&h;
}

static __device__ __forceinline__ void split_store_h2(__half* oh, __half* ol,
                                                      size_t off, float a, float b) {
    __half h0, h1, l0, l1;
    f16split(a, h0, l0);
    f16split(b, h1, l1);
    *(__half2*)(oh + off) = __halves2half2(h0, h1);
    *(__half2*)(ol + off) = __halves2half2(l0, l1);
}

// ======================= scratch (device globals) =======================
__device__ float g_x[MM * DD];

__device__ __half g_h_hi[MM * DD];
__device__ __half g_h_lo[MM * DD];
__device__ __half g_att_hi[MM * DD];
__device__ __half g_att_lo[MM * DD];
__device__ __half g_ff_hi[MM * FFD];
__device__ __half g_ff_lo[MM * FFD];
__device__ __half g_x_hi[MM * DD];

__device__ __half g_qkvh[3 * 24 * TT * HSZ];
__device__ __half g_qkvl[3 * 24 * TT * HSZ];

__device__ __half g_wqkvT_hi[LL * 3 * DD * DD];
__device__ __half g_wqkvT_lo[LL * 3 * DD * DD];
__device__ __half g_woT_hi[LL * DD * DD];
__device__ __half g_woT_lo[LL * DD * DD];
__device__ __half g_w1T_hi[LL * FFD * DD];
__device__ __half g_w1T_lo[LL * FFD * DD];
__device__ __half g_w2T_hi[LL * DD * FFD];
__device__ __half g_w2T_lo[LL * DD * FFD];
__device__ __half g_wlmT_hi[(size_t)VV * DD];

// ======================= weight prep =======================
__global__ void prep_qkvT_k(const float* __restrict__ wq,
                            const float* __restrict__ wk,
                            const float* __restrict__ wv) {
    int i = blockIdx.x * blockDim.x + threadIdx.x;
    const int total = LL * 3 * DD * DD;
    if (i >= total) return;
    int d = i % DD;
    int n = (i / DD) % (3 * DD);
    int l = i / (DD * 3 * DD);
    int sel = n / DD;
    int h = (n % DD) / HSZ;
    int e = n % HSZ;
    size_t src = (((size_t)l * HH + h) * DD + d) * HSZ + e;
    float v = (sel == 0) ? wq[src] : (sel == 1) ? wk[src] : wv[src];
    __half hi, lo;
    f16split(v, hi, lo);
    g_wqkvT_hi[i] = hi;
    g_wqkvT_lo[i] = lo;
}

__global__ void tsplit_k(const float* __restrict__ in,
                         __half* __restrict__ oh, __half* __restrict__ ol,
                         int K, int N) {
    __shared__ float tile[32][33];
    size_t zofs = (size_t)blockIdx.z * K * N;
    in += zofs; oh += zofs; ol += zofs;
    int tx = threadIdx.x, ty = threadIdx.y;
    int x = blockIdx.x * 32 + tx;
    int y0 = blockIdx.y * 32;
    #pragma unroll
    for (int j = 0; j < 32; j += 8)
        tile[ty + j][tx] = in[(size_t)(y0 + ty + j) * N + x];
    __syncthreads();
    #pragma unroll
    for (int j = 0; j < 32; j += 8) {
        float v = tile[tx][ty + j];
        __half hi, lo;
        f16split(v, hi, lo);
        size_t o = (size_t)(blockIdx.x * 32 + ty + j) * K + y0 + tx;
        oh[o] = hi;
        ol[o] = lo;
    }
}

// hi-only transpose (LM-head weights: lo part is dead with TERMS=1)
__global__ void tsplit_hi_k(const float* __restrict__ in,
                            __half* __restrict__ oh, int K, int N) {
    __shared__ float tile[32][33];
    int tx = threadIdx.x, ty = threadIdx.y;
    int x = blockIdx.x * 32 + tx;
    int y0 = blockIdx.y * 32;
    #pragma unroll
    for (int j = 0; j < 32; j += 8)
        tile[ty + j][tx] = in[(size_t)(y0 + ty + j) * N + x];
    __syncthreads();
    #pragma unroll
    for (int j = 0; j < 32; j += 8) {
        float v = tile[tx][ty + j];
        size_t o = (size_t)(blockIdx.x * 32 + ty + j) * K + y0 + tx;
        oh[o] = __float2half_rn(v);
    }
}

// ======================= embedding =======================
__global__ void embed_k(const int* __restrict__ idx,
                        const float* __restrict__ tok,
                        const float* __restrict__ pos) {
    int i = blockIdx.x * blockDim.x + threadIdx.x;
    if (i >= MM * DD) return;
    int d = i % DD;
    int m = i / DD;
    int t = m % TT;
    g_x[i] = tok[(size_t)idx[m] * DD + d] + pos[t * DD + d];
}

// ======================= layernorm -> split fp16 =======================
__global__ void layernorm_k(const float* __restrict__ x,
                            const float* __restrict__ g,
                            const float* __restrict__ b,
                            __half* __restrict__ oh, __half* __restrict__ ol) {
    int row = blockIdx.x;
    const float* xr = x + (size_t)row * DD;
    int tid = threadIdx.x;  // 256
    float v0 = xr[tid], v1 = xr[tid + 256], v2 = xr[tid + 512];
    float s = v0 + v1 + v2;
    float sq = v0 * v0 + v1 * v1 + v2 * v2;
    __shared__ float shs[8], shq[8];
    #pragma unroll
    for (int o = 16; o; o >>= 1) {
        s  += __shfl_xor_sync(0xffffffffu, s, o);
        sq += __shfl_xor_sync(0xffffffffu, sq, o);
    }
    if ((tid & 31) == 0) { shs[tid >> 5] = s; shq[tid >> 5] = sq; }
    __syncthreads();
    if (tid < 32) {
        s  = (tid < 8) ? shs[tid] : 0.f;
        sq = (tid < 8) ? shq[tid] : 0.f;
        #pragma unroll
        for (int o = 4; o; o >>= 1) {
            s  += __shfl_xor_sync(0xffffffffu, s, o);
            sq += __shfl_xor_sync(0xffffffffu, sq, o);
        }
        if (tid == 0) { shs[0] = s; shq[0] = sq; }
    }
    __syncthreads();
    float mean = shs[0] * (1.f / DD);
    float var  = shq[0] * (1.f / DD) - mean * mean;
    float r = rsqrtf(var + 1e-5f);
    size_t base = (size_t)row * DD;
    #pragma unroll
    for (int u = 0; u < 3; u++) {
        int c = tid + u * 256;
        float v = (u == 0) ? v0 : (u == 1) ? v1 : v2;
        float y = (v - mean) * r * g[c] + b[c];
        __half hi, lo;
        f16split(y, hi, lo);
        oh[base + c] = hi;
        ol[base + c] = lo;
    }
}

// ======================= fp16-split GEMM (BK=32, 2-stage) ==================
// BM = 128 (256 thr, 2 CTAs/SM) or 64 (128 thr, 3 CTAs/SM — for N=768 GEMMs)
// TERMS=3: ah*bh + ah*bl + al*bh ; TERMS=2: ah*bh + ah*bl ; TERMS=1: ah*bh
// EPI: 1 bias->C ; 2 bias+relu->split ; 3 bias+res->C ; 4 qkv scatter ;
//      6 bias+res->C + hi-only split
#define GEMM_SMEM_128 (2 * 40960)
#define GEMM_SMEM_64  (2 * 30720)

template <int EPI, int TERMS, int BM>
__global__ void __launch_bounds__(BM == 64 ? 128 : 256, BM == 64 ? 3 : 2)
gemm2_k(int M, int N, int K,
        const __half* __restrict__ Ahi, const __half* __restrict__ Alo,
        const __half* __restrict__ Bhi, const __half* __restrict__ Blo,
        const float* __restrict__ bias, const float* __restrict__ res,
        float* __restrict__ C,
        __half* __restrict__ outh, __half* __restrict__ outl) {
    constexpr int A_LO   = (BM == 64) ? 5120  : 10240;
    constexpr int B_HI   = (BM == 64) ? 10240 : 20480;
    constexpr int B_PITCH = 10240;
    constexpr int STAGE  = (BM == 64) ? 30720 : 40960;

    extern __shared__ __align__(16) char smem[];
    const uint32_t sb = smem_u32(smem);
    const int tid = threadIdx.x;
    const int wid = tid >> 5, lid = tid & 31;
    const int g = lid >> 2, t4 = lid & 3;
    const int wm = (BM == 64) ? 0 : (wid & 1);
    const int wn = (BM == 64) ? wid : (wid >> 1);
    const int m_off = wm * 64, n_off = wn * 32;

    int bx, by;
    {
        int gid = blockIdx.y * gridDim.x + blockIdx.x;
        int nb = gridDim.x * 4;
        int band = gid / nb;
        int rem = gid % nb;
        by = band * 4 + (rem & 3);
        bx = rem >> 2;
    }
    const int row0 = by * BM, col0 = bx * 128;
    const __half* src[4] = { Ahi + (size_t)row0 * K, Alo + (size_t)row0 * K,
                             Bhi + (size_t)col0 * K, Blo + (size_t)col0 * K };

    const int row_off = lid & 15;
    const int half16  = (lid >> 4) * 16;
    const uint32_t aBase = sb + (m_off + row_off) * 80 + half16;
    const uint32_t bBase = sb + B_HI + (n_off + row_off) * 80 + half16;

    const int r0 = tid >> 2;
    const int c8 = (tid & 3) * 8;
    const int cB = (tid & 3) * 16;

    float acc[4][4][4];
    #pragma unroll
    for (int i = 0; i < 4; i++)
        #pragma unroll
        for (int j = 0; j < 4; j++)
            #pragma unroll
            for (int q = 0; q < 4; q++) acc[i][j][q] = 0.f;

    const int KT = K >> 5;

    auto issue_stage = [&](uint32_t base, int tk) {
        if (BM == 64) {
            #pragma unroll
            for (int mat = 0; mat < 2; mat++) {
                if (TERMS <= 2 && mat == 1) continue;
                const __half* s = src[mat];
                cp_async16(base + mat * A_LO + r0 * 80 + cB,
                           s + (size_t)r0 * K + tk + c8);
                cp_async16(base + mat * A_LO + (r0 + 32) * 80 + cB,
                           s + (size_t)(r0 + 32) * K + tk + c8);
            }
            #pragma unroll
            for (int mat = 0; mat < 2; mat++) {
                if (TERMS == 1 && mat == 1) continue;
                const __half* s = src[2 + mat];
                #pragma unroll
                for (int rr = 0; rr < 4; rr++)
                    cp_async16(base + B_HI + mat * B_PITCH + (r0 + rr * 32) * 80 + cB,
                               s + (size_t)(r0 + rr * 32) * K + tk + c8);
            }
        } else {
            #pragma unroll
            for (int mat = 0; mat < 4; mat++) {
                if (TERMS <= 2 && mat == 1) continue;
                if (TERMS == 1 && mat == 3) continue;
                const __half* s = src[mat];
                uint32_t mb = base + ((mat < 2) ? mat * A_LO : B_HI + (mat - 2) * B_PITCH);
                cp_async16(mb + r0 * 80 + cB, s + (size_t)r0 * K + tk + c8);
                cp_async16(mb + (r0 + 64) * 80 + cB,
                           s + (size_t)(r0 + 64) * K + tk + c8);
            }
        }
        asm volatile("cp.async.commit_group;" ::: "memory");
    };

    issue_stage(sb, 0);

    for (int t = 0; t < KT; t++) {
        const int cur = t & 1;
        asm volatile("cp.async.wait_group 0;" ::: "memory");
        __syncthreads();
        if (t + 1 < KT)
            issue_stage(sb + (cur ^ 1) * STAGE, (t + 1) * 32);

        const uint32_t aA = aBase + cur * STAGE;
        const uint32_t bA = bBase + cur * STAGE;
        #pragma unroll
        for (int kb = 0; kb < 2; kb++) {
            uint32_t bh[4][2], bl[4][2];
            #pragma unroll
            for (int jp = 0; jp < 2; jp++) {
                LDSM_X4(bh[2 * jp][0], bh[2 * jp + 1][0], bh[2 * jp][1], bh[2 * jp + 1][1],
                        bA + jp * 1280 + kb * 32);
                if (TERMS >= 2)
                    LDSM_X4(bl[2 * jp][0], bl[2 * jp + 1][0], bl[2 * jp][1], bl[2 * jp + 1][1],
                            bA + B_PITCH + jp * 1280 + kb * 32);
            }
            #pragma unroll
            for (int i = 0; i < 4; i++) {
                uint32_t ah[4], al[4];
                LDSM_X4(ah[0], ah[1], ah[2], ah[3], aA + i * 1280 + kb * 32);
                if (TERMS == 3)
                    LDSM_X4(al[0], al[1], al[2], al[3],
                            aA + A_LO + i * 1280 + kb * 32);
                #pragma unroll
                for (int j = 0; j < 4; j++)
                    mma_f16(acc[i][j], ah, bh[j]);
                if (TERMS >= 2) {
                    #pragma unroll
                    for (int j = 0; j < 4; j++)
                        mma_f16(acc[i][j], ah, bl[j]);
                }
                if (TERMS == 3) {
                    #pragma unroll
                    for (int j = 0; j < 4; j++)
                        mma_f16(acc[i][j], al, bh[j]);
                }
            }
        }
    }

    // ---- epilogue ----
    #pragma unroll
    for (int i = 0; i < 4; i++) {
        int m0 = row0 + m_off + i * 16 + g;
        #pragma unroll
        for (int j = 0; j < 4; j++) {
            int n0 = col0 + n_off + j * 8 + t4 * 2;
            float v0 = acc[i][j][0], v1 = acc[i][j][1];
            float v2 = acc[i][j][2], v3 = acc[i][j][3];
            if (EPI == 4) {
                int sel = n0 / DD;            // n0, n0+1 share sel/h (n0 even)
                int h = (n0 % DD) >> 7;
                int e = n0 & 127;
                if (sel < 2) {
                    // q/k: [t][e] layout -> e, e+1 contiguous; vectorized h2
                    #pragma unroll
                    for (int q = 0; q < 2; q++) {
                        int m = m0 + q * 8;
                        float va = q ? v2 : v0, vb = q ? v3 : v1;
                        int b = m >> 10, tt = m & 1023;
                        size_t o = ((size_t)(sel * 24 + b * HH + h) << 17) +
                                   tt * 128 + e;
                        __half ha, la, hb, lb;
                        f16split(va, ha, la);
                        f16split(vb, hb, lb);
                        *(__half2*)(outh + o) = __halves2half2(ha, hb);
                        *(__half2*)(outl + o) = __halves2half2(la, lb);
                    }
                } else {
                    // v: [e][t] layout -> scalar scatter
                    #pragma unroll
                    for (int q = 0; q < 4; q++) {
                        int m = m0 + (q >> 1) * 8;
                        int ee = e + (q & 1);
                        float v = (q == 0) ? v0 : (q == 1) ? v1 : (q == 2) ? v2 : v3;
                        int b = m >> 10, tt = m & 1023;
                        size_t o = ((size_t)(48 + b * HH + h) << 17) +
                                   (size_t)ee * 1024 + tt;
                        __half hi, lo;
                        f16split(v, hi, lo);
                        outh[o] = hi;
                        outl[o] = lo;
                    }
                }
                continue;
            }
            {
                float b0 = bias[n0], b1 = bias[n0 + 1];
                v0 += b0; v1 += b1; v2 += b0; v3 += b1;
            }
            if (EPI == 2) {
                v0 = fmaxf(v0, 0.f); v1 = fmaxf(v1, 0.f);
                v2 = fmaxf(v2, 0.f); v3 = fmaxf(v3, 0.f);
            }
            if (EPI == 3 || EPI == 6) {
                const float* r0p = res + (size_t)m0 * N + n0;
                const float* r1p = res + (size_t)(m0 + 8) * N + n0;
                v0 += r0p[0]; v1 += r0p[1]; v2 += r1p[0]; v3 += r1p[1];
            }
            if (EPI == 1 || EPI == 3 || EPI == 6) {
                *(float2*)(C + (size_t)m0 * N + n0)       = make_float2(v0, v1);
                *(float2*)(C + (size_t)(m0 + 8) * N + n0) = make_float2(v2, v3);
            }
            if (EPI == 2) {
                split_store_h2(outh, outl, (size_t)m0 * N + n0, v0, v1);
                split_store_h2(outh, outl, (size_t)(m0 + 8) * N + n0, v2, v3);
            }
            if (EPI == 6) {  // hi-only (LM-head input; lo is dead with TERMS=1)
                *(__half2*)(outh + (size_t)m0 * N + n0) =
                    __halves2half2(__float2half_rn(v0), __float2half_rn(v1));
                *(__half2*)(outh + (size_t)(m0 + 8) * N + n0) =
                    __halves2half2(__float2half_rn(v2), __float2half_rn(v3));
            }
        }
    }
}

// ======================= fused flash attention =======================
#define AQ_H 0
#define AQ_L 17408
#define AK_H 34816
#define AK_L 52224
#define AV_H 69632
#define AV_L 88064
#define ATT_SMEM 106496

__global__ void __launch_bounds__(128)
flash_attn_k(const __half* __restrict__ qkvh, const __half* __restrict__ qkvl,
             __half* __restrict__ atth, __half* __restrict__ attl) {
    extern __shared__ __align__(16) char smem[];
    const uint32_t sb = smem_u32(smem);
    const int bh = blockIdx.y;
    const int qt = 15 - blockIdx.x;
    const int tid = threadIdx.x;
    const int wid = tid >> 5, lid = tid & 31;
    const int g = lid >> 2, t4 = lid & 3;
    const int row_off = lid & 15;
    const int half16 = (lid >> 4) * 16;

    const __half* qh = qkvh + ((size_t)bh << 17) + qt * 64 * 128;
    const __half* ql = qkvl + ((size_t)bh << 17) + qt * 64 * 128;
    #pragma unroll
    for (int it = 0; it < 8; it++) {
        int id = tid + it * 128;
        int r = id >> 4, cb = id & 15;
        cp_async16(sb + AQ_H + r * 272 + cb * 16, qh + r * 128 + cb * 8);
        cp_async16(sb + AQ_L + r * 272 + cb * 16, ql + r * 128 + cb * 8);
    }
    asm volatile("cp.async.commit_group;" ::: "memory");

    float S[8][4];
    float Oa[16][4];
    #pragma unroll
    for (int nb = 0; nb < 16; nb++)
        #pragma unroll
        for (int q = 0; q < 4; q++) Oa[nb][q] = 0.f;
    float m0 = -1e30f, m1 = -1e30f, l0 = 0.f, l1 = 0.f;
    const float scale = 0.08838834764831845f;

    const __half* kbh = qkvh + ((size_t)(24 + bh) << 17);
    const __half* kbl = qkvl + ((size_t)(24 + bh) << 17);
    const __half* vbh = qkvh + ((size_t)(48 + bh) << 17);
    const __half* vbl = qkvl + ((size_t)(48 + bh) << 17);

    for (int kt = 0; kt <= qt; kt++) {
        const __half* kh = kbh + kt * 64 * 128;
        const __half* kl = kbl + kt * 64 * 128;
        // K group (needed for S)
        #pragma unroll
        for (int it = 0; it < 8; it++) {
            int id = tid + it * 128;
            int r = id >> 4, cb = id & 15;
            cp_async16(sb + AK_H + r * 272 + cb * 16, kh + r * 128 + cb * 8);
            cp_async16(sb + AK_L + r * 272 + cb * 16, kl + r * 128 + cb * 8);
        }
        asm volatile("cp.async.commit_group;" ::: "memory");
        // V group (needed only at PV — may stay in flight during S compute)
        #pragma unroll
        for (int it = 0; it < 8; it++) {
            int id = tid + it * 128;
            int e = id >> 3, cb = id & 7;
            cp_async16(sb + AV_H + e * 144 + cb * 16,
                       vbh + (size_t)e * 1024 + kt * 64 + cb * 8);
            cp_async16(sb + AV_L + e * 144 + cb * 16,
                       vbl + (size_t)e * 1024 + kt * 64 + cb * 8);
        }
        asm volatile("cp.async.commit_group;" ::: "memory");
        // wait for Q (first iter) + K; allow V group outstanding
        asm volatile("cp.async.wait_group 1;" ::: "memory");
        __syncthreads();

        #pragma unroll
        for (int j = 0; j < 8; j++)
            #pragma unroll
            for (int q = 0; q < 4; q++) S[j][q] = 0.f;
        #pragma unroll
        for (int kb = 0; kb < 8; kb++) {
            uint32_t ah[4], al[4];
            uint32_t qAddr = sb + AQ_H + (wid * 16 + row_off) * 272 + kb * 32 + half16;
            LDSM_X4(ah[0], ah[1], ah[2], ah[3], qAddr);
            LDSM_X4(al[0], al[1], al[2], al[3], qAddr + (AQ_L - AQ_H));
            #pragma unroll
            for (int np = 0; np < 4; np++) {
                uint32_t bh0[2], bh1[2], bl0[2], bl1[2];
                uint32_t kAddr = sb + AK_H + (np * 16 + row_off) * 272 + kb * 32 + half16;
                LDSM_X4(bh0[0], bh1[0], bh0[1], bh1[1], kAddr);
                LDSM_X4(bl0[0], bl1[0], bl0[1], bl1[1], kAddr + (AK_L - AK_H));
                mma_f16(S[2 * np],     ah, bh0);
                mma_f16(S[2 * np + 1], ah, bh1);
                mma_f16(S[2 * np],     ah, bl0);
                mma_f16(S[2 * np + 1], ah, bl1);
                mma_f16(S[2 * np],     al, bh0);
                mma_f16(S[2 * np + 1], al, bh1);
            }
        }

        float mx0 = -1e30f, mx1 = -1e30f;
        #pragma unroll
        for (int j = 0; j < 8; j++) {
            #pragma unroll
            for (int q = 0; q < 4; q++) {
                float sv = S[j][q] * scale;
                if (kt == qt) {
                    int col = j * 8 + t4 * 2 + (q & 1);
                    int row = wid * 16 + g + (q >> 1) * 8;
                    if (col > row) sv = -1e30f;
                }
                S[j][q] = sv;
                if (q < 2) mx0 = fmaxf(mx0, sv);
                else       mx1 = fmaxf(mx1, sv);
            }
        }
        mx0 = fmaxf(mx0, __shfl_xor_sync(0xffffffffu, mx0, 1));
        mx0 = fmaxf(mx0, __shfl_xor_sync(0xffffffffu, mx0, 2));
        mx1 = fmaxf(mx1, __shfl_xor_sync(0xffffffffu, mx1, 1));
        mx1 = fmaxf(mx1, __shfl_xor_sync(0xffffffffu, mx1, 2));
        float mn0 = fmaxf(m0, mx0), mn1 = fmaxf(m1, mx1);
        float alpha0 = __expf(m0 - mn0), alpha1 = __expf(m1 - mn1);
        float sum0 = 0.f, sum1 = 0.f;
        #pragma unroll
        for (int j = 0; j < 8; j++) {
            float p0 = __expf(S[j][0] - mn0);
            float p1 = __expf(S[j][1] - mn0);
            float p2 = __expf(S[j][2] - mn1);
            float p3 = __expf(S[j][3] - mn1);
            S[j][0] = p0; S[j][1] = p1; S[j][2] = p2; S[j][3] = p3;
            sum0 += p0 + p1; sum1 += p2 + p3;
        }
        sum0 += __shfl_xor_sync(0xffffffffu, sum0, 1);
        sum0 += __shfl_xor_sync(0xffffffffu, sum0, 2);
        sum1 += __shfl_xor_sync(0xffffffffu, sum1, 1);
        sum1 += __shfl_xor_sync(0xffffffffu, sum1, 2);
        l0 = l0 * alpha0 + sum0;
        l1 = l1 * alpha1 + sum1;
        m0 = mn0; m1 = mn1;
        #pragma unroll
        for (int nb = 0; nb < 16; nb++) {
            Oa[nb][0] *= alpha0; Oa[nb][1] *= alpha0;
            Oa[nb][2] *= alpha1; Oa[nb][3] *= alpha1;
        }

        // V must be resident + visible to all threads before PV ldmatrix
        asm volatile("cp.async.wait_group 0;" ::: "memory");
        __syncthreads();

        #pragma unroll
        for (int kb = 0; kb < 4; kb++) {
            int j0 = 2 * kb, j1 = 2 * kb + 1;
            uint32_t pah[4], pal[4];
            {
                __half h0, h1, lo0, lo1;
                f16split(S[j0][0], h0, lo0); f16split(S[j0][1], h1, lo1);
                pah[0] = pack_h2(h0, h1);  pal[0] = pack_h2(lo0, lo1);
                f16split(S[j0][2], h0, lo0); f16split(S[j0][3], h1, lo1);
                pah[1] = pack_h2(h0, h1);  pal[1] = pack_h2(lo0, lo1);
                f16split(S[j1][0], h0, lo0); f16split(S[j1][1], h1, lo1);
                pah[2] = pack_h2(h0, h1);  pal[2] = pack_h2(lo0, lo1);
                f16split(S[j1][2], h0, lo0); f16split(S[j1][3], h1, lo1);
                pah[3] = pack_h2(h0, h1);  pal[3] = pack_h2(lo0, lo1);
            }
            #pragma unroll
            for (int ep = 0; ep < 8; ep++) {
                uint32_t vh0[2], vh1[2], vl0[2], vl1[2];
                uint32_t vAddr = sb + AV_H + (ep * 16 + row_off) * 144 + kb * 32 + half16;
                LDSM_X4(vh0[0], vh1[0], vh0[1], vh1[1], vAddr);
                LDSM_X4(vl0[0], vl1[0], vl0[1], vl1[1], vAddr + (AV_L - AV_H));
                mma_f16(Oa[2 * ep],     pah, vh0);
                mma_f16(Oa[2 * ep + 1], pah, vh1);
                mma_f16(Oa[2 * ep],     pah, vl0);
                mma_f16(Oa[2 * ep + 1], pah, vl1);
                mma_f16(Oa[2 * ep],     pal, vh0);
                mma_f16(Oa[2 * ep + 1], pal, vh1);
            }
        }
        __syncthreads();
    }

    float inv0 = 1.f / l0, inv1 = 1.f / l1;
    int b = bh / HH, h = bh % HH;
    int trow = qt * 64 + wid * 16 + g;
    size_t o0 = ((size_t)(b * TT + trow)) * DD + h * HSZ;
    size_t o1 = ((size_t)(b * TT + trow + 8)) * DD + h * HSZ;
    #pragma unroll
    for (int nb = 0; nb < 16; nb++) {
        int e = nb * 8 + t4 * 2;
        split_store_h2(atth, attl, o0 + e, Oa[nb][0] * inv0, Oa[nb][1] * inv0);
        split_store_h2(atth, attl, o1 + e, Oa[nb][2] * inv1, Oa[nb][3] * inv1);
    }
}

// ======================= host orchestration =======================
extern "C" void kernel_launch(void* const* d_in, const int* in_sizes, int n_in,
                              void* d_out, int out_size) {
    const int*   idx     = (const int*)d_in[0];
    const float* tok_emb = (const float*)d_in[1];
    const float* pos_emb = (const float*)d_in[2];
    const float* wq      = (const float*)d_in[3];
    const float* wk      = (const float*)d_in[4];
    const float* wv      = (const float*)d_in[5];
    const float* wo      = (const float*)d_in[6];
    const float* bo      = (const float*)d_in[7];
    const float* w1      = (const float*)d_in[8];
    const float* b1      = (const float*)d_in[9];
    const float* w2      = (const float*)d_in[10];
    const float* b2      = (const float*)d_in[11];
    const float* g1      = (const float*)d_in[12];
    const float* be1     = (const float*)d_in[13];
    const float* g2      = (const float*)d_in[14];
    const float* be2     = (const float*)d_in[15];
    const float* wlm     = (const float*)d_in[16];
    const float* blm     = (const float*)d_in[17];
    float* out = (float*)d_out;

    float* px;
    __half *ph_h, *ph_l, *patt_h, *patt_l, *pff_h, *pff_l, *px_h;
    __half *pqkvh, *pqkvl;
    __half *pqkvT_h, *pqkvT_l, *pwoT_h, *pwoT_l, *pw1T_h, *pw1T_l,
           *pw2T_h, *pw2T_l, *plmT_h;
    cudaGetSymbolAddress((void**)&px,     g_x);
    cudaGetSymbolAddress((void**)&ph_h,   g_h_hi);
    cudaGetSymbolAddress((void**)&ph_l,   g_h_lo);
    cudaGetSymbolAddress((void**)&patt_h, g_att_hi);
    cudaGetSymbolAddress((void**)&patt_l, g_att_lo);
    cudaGetSymbolAddress((void**)&pff_h,  g_ff_hi);
    cudaGetSymbolAddress((void**)&pff_l,  g_ff_lo);
    cudaGetSymbolAddress((void**)&px_h,   g_x_hi);
    cudaGetSymbolAddress((void**)&pqkvh,  g_qkvh);
    cudaGetSymbolAddress((void**)&pqkvl,  g_qkvl);
    cudaGetSymbolAddress((void**)&pqkvT_h, g_wqkvT_hi);
    cudaGetSymbolAddress((void**)&pqkvT_l, g_wqkvT_lo);
    cudaGetSymbolAddress((void**)&pwoT_h,  g_woT_hi);
    cudaGetSymbolAddress((void**)&pwoT_l,  g_woT_lo);
    cudaGetSymbolAddress((void**)&pw1T_h,  g_w1T_hi);
    cudaGetSymbolAddress((void**)&pw1T_l,  g_w1T_lo);
    cudaGetSymbolAddress((void**)&pw2T_h,  g_w2T_hi);
    cudaGetSymbolAddress((void**)&pw2T_l,  g_w2T_lo);
    cudaGetSymbolAddress((void**)&plmT_h,  g_wlmT_hi);

    cudaFuncSetAttribute((const void*)gemm2_k<1, 1, 128>, cudaFuncAttributeMaxDynamicSharedMemorySize, GEMM_SMEM_128);
    cudaFuncSetAttribute((const void*)gemm2_k<2, 3, 128>, cudaFuncAttributeMaxDynamicSharedMemorySize, GEMM_SMEM_128);
    cudaFuncSetAttribute((const void*)gemm2_k<4, 3, 128>, cudaFuncAttributeMaxDynamicSharedMemorySize, GEMM_SMEM_128);
    cudaFuncSetAttribute((const void*)gemm2_k<3, 3, 64>,  cudaFuncAttributeMaxDynamicSharedMemorySize, GEMM_SMEM_64);
    cudaFuncSetAttribute((const void*)gemm2_k<6, 3, 64>,  cudaFuncAttributeMaxDynamicSharedMemorySize, GEMM_SMEM_64);
    cudaFuncSetAttribute(flash_attn_k, cudaFuncAttributeMaxDynamicSharedMemorySize, ATT_SMEM);

    {
        int total = LL * 3 * DD * DD;
        prep_qkvT_k<<<(total + 255) / 256, 256>>>(wq, wk, wv);
        dim3 blk(32, 8);
        tsplit_k<<<dim3(DD / 32, DD / 32, LL), blk>>>(wo, pwoT_h, pwoT_l, DD, DD);
        tsplit_k<<<dim3(FFD / 32, DD / 32, LL), blk>>>(w1, pw1T_h, pw1T_l, DD, FFD);
        tsplit_k<<<dim3(DD / 32, FFD / 32, LL), blk>>>(w2, pw2T_h, pw2T_l, FFD, DD);
        tsplit_hi_k<<<dim3(VV / 32, DD / 32, 1), blk>>>(wlm, plmT_h, DD, VV);
        embed_k<<<(MM * DD + 255) / 256, 256>>>(idx, tok_emb, pos_emb);
    }

    for (int l = 0; l < LL; l++) {
        layernorm_k<<<MM, 256>>>(px, g1 + l * DD, be1 + l * DD, ph_h, ph_l);
        gemm2_k<4, 3, 128><<<dim3(3 * DD / 128, MM / 128), 256, GEMM_SMEM_128>>>(
            MM, 3 * DD, DD, ph_h, ph_l,
            pqkvT_h + (size_t)l * 3 * DD * DD,
            pqkvT_l + (size_t)l * 3 * DD * DD,
            nullptr, nullptr, nullptr, pqkvh, pqkvl);
        flash_attn_k<<<dim3(16, 24), 128, ATT_SMEM>>>(pqkvh, pqkvl, patt_h, patt_l);
        gemm2_k<3, 3, 64><<<dim3(DD / 128, MM / 64), 128, GEMM_SMEM_64>>>(
            MM, DD, DD, patt_h, patt_l,
            pwoT_h + (size_t)l * DD * DD,
            pwoT_l + (size_t)l * DD * DD,
            bo + l * DD, px, px, nullptr, nullptr);
        layernorm_k<<<MM, 256>>>(px, g2 + l * DD, be2 + l * DD, ph_h, ph_l);
        gemm2_k<2, 3, 128><<<dim3(FFD / 128, MM / 128), 256, GEMM_SMEM_128>>>(
            MM, FFD, DD, ph_h, ph_l,
            pw1T_h + (size_t)l * FFD * DD,
            pw1T_l + (size_t)l * FFD * DD,
            b1 + l * FFD, nullptr, nullptr, pff_h, pff_l);
        if (l < LL - 1) {
            gemm2_k<3, 3, 64><<<dim3(DD / 128, MM / 64), 128, GEMM_SMEM_64>>>(
                MM, DD, FFD, pff_h, pff_l,
                pw2T_h + (size_t)l * DD * FFD,
                pw2T_l + (size_t)l * DD * FFD,
                b2 + l * DD, px, px, nullptr, nullptr);
        } else {
            gemm2_k<6, 3, 64><<<dim3(DD / 128, MM / 64), 128, GEMM_SMEM_64>>>(
                MM, DD, FFD, pff_h, pff_l,
                pw2T_h + (size_t)l * DD * FFD,
                pw2T_l + (size_t)l * DD * FFD,
                b2 + l * DD, px, px, px_h, nullptr);
        }
    }

    // LM head (final op): 1-term fp16, BM=128 tile
    gemm2_k<1, 1, 128><<<dim3(VV / 128, MM / 128), 256, GEMM_SMEM_128>>>(
        MM, VV, DD, px_h, nullptr, plmT_h, nullptr, blm, nullptr, out,
        nullptr, nullptr);
}

// round 17
// speedup vs baseline: 1.0447x; 1.0011x over previous
#include <cuda_runtime.h>
#include <cuda_fp16.h>
#include <cstdint>

#define DD   768
#define TT   1024
#define BBATCH 4
#define MM   4096          // B*T
#define HH   6
#define HSZ  128
#define FFD  3072
#define VV   32000
#define LL   6

// ======================= helpers =======================
static __device__ __forceinline__ uint32_t smem_u32(const void* p) {
    uint32_t a;
    asm("{ .reg .u64 t; cvta.to.shared.u64 t, %1; cvt.u32.u64 %0, t; }"
        : "=r"(a) : "l"(p));
    return a;
}

static __device__ __forceinline__ void cp_async16(uint32_t dst_smem, const void* src) {
    asm volatile("cp.async.cg.shared.global [%0], [%1], 16;"
                 :: "r"(dst_smem), "l"(src) : "memory");
}

static __device__ __forceinline__ void mma_f16(float* d, const uint32_t* a,
                                               const uint32_t* b) {
    asm volatile(
        "mma.sync.aligned.m16n8k16.row.col.f32.f16.f16.f32 "
        "{%0,%1,%2,%3}, {%4,%5,%6,%7}, {%8,%9}, {%0,%1,%2,%3};"
        : "+f"(d[0]), "+f"(d[1]), "+f"(d[2]), "+f"(d[3])
        : "r"(a[0]), "r"(a[1]), "r"(a[2]), "r"(a[3]), "r"(b[0]), "r"(b[1]));
}

#define LDSM_X4(R0, R1, R2, R3, ADDR) \
    asm volatile("ldmatrix.sync.aligned.m8n8.x4.shared.b16 {%0,%1,%2,%3}, [%4];" \
                 : "=r"(R0), "=r"(R1), "=r"(R2), "=r"(R3) : "r"(ADDR))

static __device__ __forceinline__ void f16split(float a, __half& hi, __half& lo) {
    hi = __float2half_rn(a);
    lo = __float2half_rn(a - __half2float(hi));
}

static __device__ __forceinline__ uint32_t pack_h2(__half a, __half b) {
    __half2 h = __halves2half2(a, b);
    return *(uint32_t*)&h;
}

static __device__ __forceinline__ void split_store_h2(__half* oh, __half* ol,
                                                      size_t off, float a, float b) {
    __half h0, h1, l0, l1;
    f16split(a, h0, l0);
    f16split(b, h1, l1);
    *(__half2*)(oh + off) = __halves2half2(h0, h1);
    *(__half2*)(ol + off) = __halves2half2(l0, l1);
}

// streaming (evict-first) fp32x2 store — for never-re-read output streams
static __device__ __forceinline__ void stg_cs_f2(float* p, float a, float b) {
    asm volatile("st.global.cs.v2.f32 [%0], {%1, %2};"
                 :: "l"(p), "f"(a), "f"(b) : "memory");
}

// ======================= scratch (device globals) =======================
__device__ float g_x[MM * DD];

__device__ __half g_h_hi[MM * DD];
__device__ __half g_h_lo[MM * DD];
__device__ __half g_att_hi[MM * DD];
__device__ __half g_att_lo[MM * DD];
__device__ __half g_ff_hi[MM * FFD];
__device__ __half g_ff_lo[MM * FFD];
__device__ __half g_x_hi[MM * DD];

__device__ __half g_qkvh[3 * 24 * TT * HSZ];
__device__ __half g_qkvl[3 * 24 * TT * HSZ];

__device__ __half g_wqkvT_hi[LL * 3 * DD * DD];
__device__ __half g_wqkvT_lo[LL * 3 * DD * DD];
__device__ __half g_woT_hi[LL * DD * DD];
__device__ __half g_woT_lo[LL * DD * DD];
__device__ __half g_w1T_hi[LL * FFD * DD];
__device__ __half g_w1T_lo[LL * FFD * DD];
__device__ __half g_w2T_hi[LL * DD * FFD];
__device__ __half g_w2T_lo[LL * DD * FFD];
__device__ __half g_wlmT_hi[(size_t)VV * DD];

// ======================= weight prep =======================
__global__ void prep_qkvT_k(const float* __restrict__ wq,
                            const float* __restrict__ wk,
                            const float* __restrict__ wv) {
    int i = blockIdx.x * blockDim.x + threadIdx.x;
    const int total = LL * 3 * DD * DD;
    if (i >= total) return;
    int d = i % DD;
    int n = (i / DD) % (3 * DD);
    int l = i / (DD * 3 * DD);
    int sel = n / DD;
    int h = (n % DD) / HSZ;
    int e = n % HSZ;
    size_t src = (((size_t)l * HH + h) * DD + d) * HSZ + e;
    float v = (sel == 0) ? wq[src] : (sel == 1) ? wk[src] : wv[src];
    __half hi, lo;
    f16split(v, hi, lo);
    g_wqkvT_hi[i] = hi;
    g_wqkvT_lo[i] = lo;
}

__global__ void tsplit_k(const float* __restrict__ in,
                         __half* __restrict__ oh, __half* __restrict__ ol,
                         int K, int N) {
    __shared__ float tile[32][33];
    size_t zofs = (size_t)blockIdx.z * K * N;
    in += zofs; oh += zofs; ol += zofs;
    int tx = threadIdx.x, ty = threadIdx.y;
    int x = blockIdx.x * 32 + tx;
    int y0 = blockIdx.y * 32;
    #pragma unroll
    for (int j = 0; j < 32; j += 8)
        tile[ty + j][tx] = in[(size_t)(y0 + ty + j) * N + x];
    __syncthreads();
    #pragma unroll
    for (int j = 0; j < 32; j += 8) {
        float v = tile[tx][ty + j];
        __half hi, lo;
        f16split(v, hi, lo);
        size_t o = (size_t)(blockIdx.x * 32 + ty + j) * K + y0 + tx;
        oh[o] = hi;
        ol[o] = lo;
    }
}

// hi-only transpose (LM-head weights: lo part is dead with TERMS=1)
__global__ void tsplit_hi_k(const float* __restrict__ in,
                            __half* __restrict__ oh, int K, int N) {
    __shared__ float tile[32][33];
    int tx = threadIdx.x, ty = threadIdx.y;
    int x = blockIdx.x * 32 + tx;
    int y0 = blockIdx.y * 32;
    #pragma unroll
    for (int j = 0; j < 32; j += 8)
        tile[ty + j][tx] = in[(size_t)(y0 + ty + j) * N + x];
    __syncthreads();
    #pragma unroll
    for (int j = 0; j < 32; j += 8) {
        float v = tile[tx][ty + j];
        size_t o = (size_t)(blockIdx.x * 32 + ty + j) * K + y0 + tx;
        oh[o] = __float2half_rn(v);
    }
}

// ======================= embedding =======================
__global__ void embed_k(const int* __restrict__ idx,
                        const float* __restrict__ tok,
                        const float* __restrict__ pos) {
    int i = blockIdx.x * blockDim.x + threadIdx.x;
    if (i >= MM * DD) return;
    int d = i % DD;
    int m = i / DD;
    int t = m % TT;
    g_x[i] = tok[(size_t)idx[m] * DD + d] + pos[t * DD + d];
}

// ======================= layernorm -> split fp16 =======================
__global__ void layernorm_k(const float* __restrict__ x,
                            const float* __restrict__ g,
                            const float* __restrict__ b,
                            __half* __restrict__ oh, __half* __restrict__ ol) {
    int row = blockIdx.x;
    const float* xr = x + (size_t)row * DD;
    int tid = threadIdx.x;  // 256
    float v0 = xr[tid], v1 = xr[tid + 256], v2 = xr[tid + 512];
    float s = v0 + v1 + v2;
    float sq = v0 * v0 + v1 * v1 + v2 * v2;
    __shared__ float shs[8], shq[8];
    #pragma unroll
    for (int o = 16; o; o >>= 1) {
        s  += __shfl_xor_sync(0xffffffffu, s, o);
        sq += __shfl_xor_sync(0xffffffffu, sq, o);
    }
    if ((tid & 31) == 0) { shs[tid >> 5] = s; shq[tid >> 5] = sq; }
    __syncthreads();
    if (tid < 32) {
        s  = (tid < 8) ? shs[tid] : 0.f;
        sq = (tid < 8) ? shq[tid] : 0.f;
        #pragma unroll
        for (int o = 4; o; o >>= 1) {
            s  += __shfl_xor_sync(0xffffffffu, s, o);
            sq += __shfl_xor_sync(0xffffffffu, sq, o);
        }
        if (tid == 0) { shs[0] = s; shq[0] = sq; }
    }
    __syncthreads();
    float mean = shs[0] * (1.f / DD);
    float var  = shq[0] * (1.f / DD) - mean * mean;
    float r = rsqrtf(var + 1e-5f);
    size_t base = (size_t)row * DD;
    #pragma unroll
    for (int u = 0; u < 3; u++) {
        int c = tid + u * 256;
        float v = (u == 0) ? v0 : (u == 1) ? v1 : v2;
        float y = (v - mean) * r * g[c] + b[c];
        __half hi, lo;
        f16split(y, hi, lo);
        oh[base + c] = hi;
        ol[base + c] = lo;
    }
}

// ======================= fp16-split GEMM (BK=32, 2-stage) ==================
// BM = 128 (256 thr, 2 CTAs/SM) or 64 (128 thr, 3 CTAs/SM — for N=768 GEMMs)
// TERMS=3: ah*bh + ah*bl + al*bh ; TERMS=1: ah*bh (final op only)
// EPI: 1 bias->C (streaming) ; 2 bias+relu->split ; 3 bias+res->C ;
//      4 qkv scatter ; 7 bias+res -> hi-only split (fp32 x store is dead)
#define GEMM_SMEM_128 (2 * 40960)
#define GEMM_SMEM_64  (2 * 30720)

template <int EPI, int TERMS, int BM>
__global__ void __launch_bounds__(BM == 64 ? 128 : 256, BM == 64 ? 3 : 2)
gemm2_k(int M, int N, int K,
        const __half* __restrict__ Ahi, const __half* __restrict__ Alo,
        const __half* __restrict__ Bhi, const __half* __restrict__ Blo,
        const float* __restrict__ bias, const float* __restrict__ res,
        float* __restrict__ C,
        __half* __restrict__ outh, __half* __restrict__ outl) {
    constexpr int A_LO   = (BM == 64) ? 5120  : 10240;
    constexpr int B_HI   = (BM == 64) ? 10240 : 20480;
    constexpr int B_PITCH = 10240;
    constexpr int STAGE  = (BM == 64) ? 30720 : 40960;

    extern __shared__ __align__(16) char smem[];
    const uint32_t sb = smem_u32(smem);
    const int tid = threadIdx.x;
    const int wid = tid >> 5, lid = tid & 31;
    const int g = lid >> 2, t4 = lid & 3;
    const int wm = (BM == 64) ? 0 : (wid & 1);
    const int wn = (BM == 64) ? wid : (wid >> 1);
    const int m_off = wm * 64, n_off = wn * 32;

    int bx, by;
    {
        int gid = blockIdx.y * gridDim.x + blockIdx.x;
        int nb = gridDim.x * 4;
        int band = gid / nb;
        int rem = gid % nb;
        by = band * 4 + (rem & 3);
        bx = rem >> 2;
    }
    const int row0 = by * BM, col0 = bx * 128;
    const __half* src[4] = { Ahi + (size_t)row0 * K, Alo + (size_t)row0 * K,
                             Bhi + (size_t)col0 * K, Blo + (size_t)col0 * K };

    const int row_off = lid & 15;
    const int half16  = (lid >> 4) * 16;
    const uint32_t aBase = sb + (m_off + row_off) * 80 + half16;
    const uint32_t bBase = sb + B_HI + (n_off + row_off) * 80 + half16;

    const int r0 = tid >> 2;
    const int c8 = (tid & 3) * 8;
    const int cB = (tid & 3) * 16;

    float acc[4][4][4];
    #pragma unroll
    for (int i = 0; i < 4; i++)
        #pragma unroll
        for (int j = 0; j < 4; j++)
            #pragma unroll
            for (int q = 0; q < 4; q++) acc[i][j][q] = 0.f;

    const int KT = K >> 5;

    auto issue_stage = [&](uint32_t base, int tk) {
        if (BM == 64) {
            #pragma unroll
            for (int mat = 0; mat < 2; mat++) {
                if (TERMS == 1 && mat == 1) continue;
                const __half* s = src[mat];
                cp_async16(base + mat * A_LO + r0 * 80 + cB,
                           s + (size_t)r0 * K + tk + c8);
                cp_async16(base + mat * A_LO + (r0 + 32) * 80 + cB,
                           s + (size_t)(r0 + 32) * K + tk + c8);
            }
            #pragma unroll
            for (int mat = 0; mat < 2; mat++) {
                if (TERMS == 1 && mat == 1) continue;
                const __half* s = src[2 + mat];
                #pragma unroll
                for (int rr = 0; rr < 4; rr++)
                    cp_async16(base + B_HI + mat * B_PITCH + (r0 + rr * 32) * 80 + cB,
                               s + (size_t)(r0 + rr * 32) * K + tk + c8);
            }
        } else {
            #pragma unroll
            for (int mat = 0; mat < 4; mat++) {
                if (TERMS == 1 && (mat == 1 || mat == 3)) continue;
                const __half* s = src[mat];
                uint32_t mb = base + ((mat < 2) ? mat * A_LO : B_HI + (mat - 2) * B_PITCH);
                cp_async16(mb + r0 * 80 + cB, s + (size_t)r0 * K + tk + c8);
                cp_async16(mb + (r0 + 64) * 80 + cB,
                           s + (size_t)(r0 + 64) * K + tk + c8);
            }
        }
        asm volatile("cp.async.commit_group;" ::: "memory");
    };

    issue_stage(sb, 0);

    for (int t = 0; t < KT; t++) {
        const int cur = t & 1;
        asm volatile("cp.async.wait_group 0;" ::: "memory");
        __syncthreads();
        if (t + 1 < KT)
            issue_stage(sb + (cur ^ 1) * STAGE, (t + 1) * 32);

        const uint32_t aA = aBase + cur * STAGE;
        const uint32_t bA = bBase + cur * STAGE;
        #pragma unroll
        for (int kb = 0; kb < 2; kb++) {
            uint32_t bh[4][2], bl[4][2];
            #pragma unroll
            for (int jp = 0; jp < 2; jp++) {
                LDSM_X4(bh[2 * jp][0], bh[2 * jp + 1][0], bh[2 * jp][1], bh[2 * jp + 1][1],
                        bA + jp * 1280 + kb * 32);
                if (TERMS == 3)
                    LDSM_X4(bl[2 * jp][0], bl[2 * jp + 1][0], bl[2 * jp][1], bl[2 * jp + 1][1],
                            bA + B_PITCH + jp * 1280 + kb * 32);
            }
            #pragma unroll
            for (int i = 0; i < 4; i++) {
                uint32_t ah[4], al[4];
                LDSM_X4(ah[0], ah[1], ah[2], ah[3], aA + i * 1280 + kb * 32);
                if (TERMS == 3)
                    LDSM_X4(al[0], al[1], al[2], al[3],
                            aA + A_LO + i * 1280 + kb * 32);
                #pragma unroll
                for (int j = 0; j < 4; j++)
                    mma_f16(acc[i][j], ah, bh[j]);
                if (TERMS == 3) {
                    #pragma unroll
                    for (int j = 0; j < 4; j++)
                        mma_f16(acc[i][j], ah, bl[j]);
                    #pragma unroll
                    for (int j = 0; j < 4; j++)
                        mma_f16(acc[i][j], al, bh[j]);
                }
            }
        }
    }

    // ---- epilogue ----
    #pragma unroll
    for (int i = 0; i < 4; i++) {
        int m0 = row0 + m_off + i * 16 + g;
        #pragma unroll
        for (int j = 0; j < 4; j++) {
            int n0 = col0 + n_off + j * 8 + t4 * 2;
            float v0 = acc[i][j][0], v1 = acc[i][j][1];
            float v2 = acc[i][j][2], v3 = acc[i][j][3];
            if (EPI == 4) {
                int sel = n0 / DD;            // n0, n0+1 share sel/h (n0 even)
                int h = (n0 % DD) >> 7;
                int e = n0 & 127;
                if (sel < 2) {
                    #pragma unroll
                    for (int q = 0; q < 2; q++) {
                        int m = m0 + q * 8;
                        float va = q ? v2 : v0, vb = q ? v3 : v1;
                        int b = m >> 10, tt = m & 1023;
                        size_t o = ((size_t)(sel * 24 + b * HH + h) << 17) +
                                   tt * 128 + e;
                        __half ha, la, hb, lb;
                        f16split(va, ha, la);
                        f16split(vb, hb, lb);
                        *(__half2*)(outh + o) = __halves2half2(ha, hb);
                        *(__half2*)(outl + o) = __halves2half2(la, lb);
                    }
                } else {
                    #pragma unroll
                    for (int q = 0; q < 4; q++) {
                        int m = m0 + (q >> 1) * 8;
                        int ee = e + (q & 1);
                        float v = (q == 0) ? v0 : (q == 1) ? v1 : (q == 2) ? v2 : v3;
                        int b = m >> 10, tt = m & 1023;
                        size_t o = ((size_t)(48 + b * HH + h) << 17) +
                                   (size_t)ee * 1024 + tt;
                        __half hi, lo;
                        f16split(v, hi, lo);
                        outh[o] = hi;
                        outl[o] = lo;
                    }
                }
                continue;
            }
            {
                float b0 = bias[n0], b1 = bias[n0 + 1];
                v0 += b0; v1 += b1; v2 += b0; v3 += b1;
            }
            if (EPI == 2) {
                v0 = fmaxf(v0, 0.f); v1 = fmaxf(v1, 0.f);
                v2 = fmaxf(v2, 0.f); v3 = fmaxf(v3, 0.f);
            }
            if (EPI == 3 || EPI == 7) {
                const float* r0p = res + (size_t)m0 * N + n0;
                const float* r1p = res + (size_t)(m0 + 8) * N + n0;
                v0 += r0p[0]; v1 += r0p[1]; v2 += r1p[0]; v3 += r1p[1];
            }
            if (EPI == 1) {  // LM-head logits: never re-read -> streaming store
                stg_cs_f2(C + (size_t)m0 * N + n0, v0, v1);
                stg_cs_f2(C + (size_t)(m0 + 8) * N + n0, v2, v3);
            }
            if (EPI == 3) {
                *(float2*)(C + (size_t)m0 * N + n0)       = make_float2(v0, v1);
                *(float2*)(C + (size_t)(m0 + 8) * N + n0) = make_float2(v2, v3);
            }
            if (EPI == 2) {
                split_store_h2(outh, outl, (size_t)m0 * N + n0, v0, v1);
                split_store_h2(outh, outl, (size_t)(m0 + 8) * N + n0, v2, v3);
            }
            if (EPI == 7) {  // hi-only split; fp32 x store dropped (dead)
                *(__half2*)(outh + (size_t)m0 * N + n0) =
                    __halves2half2(__float2half_rn(v0), __float2half_rn(v1));
                *(__half2*)(outh + (size_t)(m0 + 8) * N + n0) =
                    __halves2half2(__float2half_rn(v2), __float2half_rn(v3));
            }
        }
    }
}

// ======================= fused flash attention =======================
#define AQ_H 0
#define AQ_L 17408
#define AK_H 34816
#define AK_L 52224
#define AV_H 69632
#define AV_L 88064
#define ATT_SMEM 106496

__global__ void __launch_bounds__(128)
flash_attn_k(const __half* __restrict__ qkvh, const __half* __restrict__ qkvl,
             __half* __restrict__ atth, __half* __restrict__ attl) {
    extern __shared__ __align__(16) char smem[];
    const uint32_t sb = smem_u32(smem);
    const int bh = blockIdx.y;
    const int qt = 15 - blockIdx.x;
    const int tid = threadIdx.x;
    const int wid = tid >> 5, lid = tid & 31;
    const int g = lid >> 2, t4 = lid & 3;
    const int row_off = lid & 15;
    const int half16 = (lid >> 4) * 16;

    const __half* qh = qkvh + ((size_t)bh << 17) + qt * 64 * 128;
    const __half* ql = qkvl + ((size_t)bh << 17) + qt * 64 * 128;
    #pragma unroll
    for (int it = 0; it < 8; it++) {
        int id = tid + it * 128;
        int r = id >> 4, cb = id & 15;
        cp_async16(sb + AQ_H + r * 272 + cb * 16, qh + r * 128 + cb * 8);
        cp_async16(sb + AQ_L + r * 272 + cb * 16, ql + r * 128 + cb * 8);
    }
    asm volatile("cp.async.commit_group;" ::: "memory");

    float S[8][4];
    float Oa[16][4];
    #pragma unroll
    for (int nb = 0; nb < 16; nb++)
        #pragma unroll
        for (int q = 0; q < 4; q++) Oa[nb][q] = 0.f;
    float m0 = -1e30f, m1 = -1e30f, l0 = 0.f, l1 = 0.f;
    const float scale = 0.08838834764831845f;

    const __half* kbh = qkvh + ((size_t)(24 + bh) << 17);
    const __half* kbl = qkvl + ((size_t)(24 + bh) << 17);
    const __half* vbh = qkvh + ((size_t)(48 + bh) << 17);
    const __half* vbl = qkvl + ((size_t)(48 + bh) << 17);

    for (int kt = 0; kt <= qt; kt++) {
        const __half* kh = kbh + kt * 64 * 128;
        const __half* kl = kbl + kt * 64 * 128;
        #pragma unroll
        for (int it = 0; it < 8; it++) {
            int id = tid + it * 128;
            int r = id >> 4, cb = id & 15;
            cp_async16(sb + AK_H + r * 272 + cb * 16, kh + r * 128 + cb * 8);
            cp_async16(sb + AK_L + r * 272 + cb * 16, kl + r * 128 + cb * 8);
        }
        asm volatile("cp.async.commit_group;" ::: "memory");
        #pragma unroll
        for (int it = 0; it < 8; it++) {
            int id = tid + it * 128;
            int e = id >> 3, cb = id & 7;
            cp_async16(sb + AV_H + e * 144 + cb * 16,
                       vbh + (size_t)e * 1024 + kt * 64 + cb * 8);
            cp_async16(sb + AV_L + e * 144 + cb * 16,
                       vbl + (size_t)e * 1024 + kt * 64 + cb * 8);
        }
        asm volatile("cp.async.commit_group;" ::: "memory");
        asm volatile("cp.async.wait_group 1;" ::: "memory");
        __syncthreads();

        #pragma unroll
        for (int j = 0; j < 8; j++)
            #pragma unroll
            for (int q = 0; q < 4; q++) S[j][q] = 0.f;
        #pragma unroll
        for (int kb = 0; kb < 8; kb++) {
            uint32_t ah[4], al[4];
            uint32_t qAddr = sb + AQ_H + (wid * 16 + row_off) * 272 + kb * 32 + half16;
            LDSM_X4(ah[0], ah[1], ah[2], ah[3], qAddr);
            LDSM_X4(al[0], al[1], al[2], al[3], qAddr + (AQ_L - AQ_H));
            #pragma unroll
            for (int np = 0; np < 4; np++) {
                uint32_t bh0[2], bh1[2], bl0[2], bl1[2];
                uint32_t kAddr = sb + AK_H + (np * 16 + row_off) * 272 + kb * 32 + half16;
                LDSM_X4(bh0[0], bh1[0], bh0[1], bh1[1], kAddr);
                LDSM_X4(bl0[0], bl1[0], bl0[1], bl1[1], kAddr + (AK_L - AK_H));
                mma_f16(S[2 * np],     ah, bh0);
                mma_f16(S[2 * np + 1], ah, bh1);
                mma_f16(S[2 * np],     ah, bl0);
                mma_f16(S[2 * np + 1], ah, bl1);
                mma_f16(S[2 * np],     al, bh0);
                mma_f16(S[2 * np + 1], al, bh1);
            }
        }

        float mx0 = -1e30f, mx1 = -1e30f;
        #pragma unroll
        for (int j = 0; j < 8; j++) {
            #pragma unroll
            for (int q = 0; q < 4; q++) {
                float sv = S[j][q] * scale;
                if (kt == qt) {
                    int col = j * 8 + t4 * 2 + (q & 1);
                    int row = wid * 16 + g + (q >> 1) * 8;
                    if (col > row) sv = -1e30f;
                }
                S[j][q] = sv;
                if (q < 2) mx0 = fmaxf(mx0, sv);
                else       mx1 = fmaxf(mx1, sv);
            }
        }
        mx0 = fmaxf(mx0, __shfl_xor_sync(0xffffffffu, mx0, 1));
        mx0 = fmaxf(mx0, __shfl_xor_sync(0xffffffffu, mx0, 2));
        mx1 = fmaxf(mx1, __shfl_xor_sync(0xffffffffu, mx1, 1));
        mx1 = fmaxf(mx1, __shfl_xor_sync(0xffffffffu, mx1, 2));
        float mn0 = fmaxf(m0, mx0), mn1 = fmaxf(m1, mx1);
        float alpha0 = __expf(m0 - mn0), alpha1 = __expf(m1 - mn1);
        float sum0 = 0.f, sum1 = 0.f;
        #pragma unroll
        for (int j = 0; j < 8; j++) {
            float p0 = __expf(S[j][0] - mn0);
            float p1 = __expf(S[j][1] - mn0);
            float p2 = __expf(S[j][2] - mn1);
            float p3 = __expf(S[j][3] - mn1);
            S[j][0] = p0; S[j][1] = p1; S[j][2] = p2; S[j][3] = p3;
            sum0 += p0 + p1; sum1 += p2 + p3;
        }
        sum0 += __shfl_xor_sync(0xffffffffu, sum0, 1);
        sum0 += __shfl_xor_sync(0xffffffffu, sum0, 2);
        sum1 += __shfl_xor_sync(0xffffffffu, sum1, 1);
        sum1 += __shfl_xor_sync(0xffffffffu, sum1, 2);
        l0 = l0 * alpha0 + sum0;
        l1 = l1 * alpha1 + sum1;
        m0 = mn0; m1 = mn1;
        #pragma unroll
        for (int nb = 0; nb < 16; nb++) {
            Oa[nb][0] *= alpha0; Oa[nb][1] *= alpha0;
            Oa[nb][2] *= alpha1; Oa[nb][3] *= alpha1;
        }

        asm volatile("cp.async.wait_group 0;" ::: "memory");
        __syncthreads();

        #pragma unroll
        for (int kb = 0; kb < 4; kb++) {
            int j0 = 2 * kb, j1 = 2 * kb + 1;
            uint32_t pah[4], pal[4];
            {
                __half h0, h1, lo0, lo1;
                f16split(S[j0][0], h0, lo0); f16split(S[j0][1], h1, lo1);
                pah[0] = pack_h2(h0, h1);  pal[0] = pack_h2(lo0, lo1);
                f16split(S[j0][2], h0, lo0); f16split(S[j0][3], h1, lo1);
                pah[1] = pack_h2(h0, h1);  pal[1] = pack_h2(lo0, lo1);
                f16split(S[j1][0], h0, lo0); f16split(S[j1][1], h1, lo1);
                pah[2] = pack_h2(h0, h1);  pal[2] = pack_h2(lo0, lo1);
                f16split(S[j1][2], h0, lo0); f16split(S[j1][3], h1, lo1);
                pah[3] = pack_h2(h0, h1);  pal[3] = pack_h2(lo0, lo1);
            }
            #pragma unroll
            for (int ep = 0; ep < 8; ep++) {
                uint32_t vh0[2], vh1[2], vl0[2], vl1[2];
                uint32_t vAddr = sb + AV_H + (ep * 16 + row_off) * 144 + kb * 32 + half16;
                LDSM_X4(vh0[0], vh1[0], vh0[1], vh1[1], vAddr);
                LDSM_X4(vl0[0], vl1[0], vl0[1], vl1[1], vAddr + (AV_L - AV_H));
                mma_f16(Oa[2 * ep],     pah, vh0);
                mma_f16(Oa[2 * ep + 1], pah, vh1);
                mma_f16(Oa[2 * ep],     pah, vl0);
                mma_f16(Oa[2 * ep + 1], pah, vl1);
                mma_f16(Oa[2 * ep],     pal, vh0);
                mma_f16(Oa[2 * ep + 1], pal, vh1);
            }
        }
        __syncthreads();
    }

    float inv0 = 1.f / l0, inv1 = 1.f / l1;
    int b = bh / HH, h = bh % HH;
    int trow = qt * 64 + wid * 16 + g;
    size_t o0 = ((size_t)(b * TT + trow)) * DD + h * HSZ;
    size_t o1 = ((size_t)(b * TT + trow + 8)) * DD + h * HSZ;
    #pragma unroll
    for (int nb = 0; nb < 16; nb++) {
        int e = nb * 8 + t4 * 2;
        split_store_h2(atth, attl, o0 + e, Oa[nb][0] * inv0, Oa[nb][1] * inv0);
        split_store_h2(atth, attl, o1 + e, Oa[nb][2] * inv1, Oa[nb][3] * inv1);
    }
}

// ======================= host orchestration =======================
extern "C" void kernel_launch(void* const* d_in, const int* in_sizes, int n_in,
                              void* d_out, int out_size) {
    const int*   idx     = (const int*)d_in[0];
    const float* tok_emb = (const float*)d_in[1];
    const float* pos_emb = (const float*)d_in[2];
    const float* wq      = (const float*)d_in[3];
    const float* wk      = (const float*)d_in[4];
    const float* wv      = (const float*)d_in[5];
    const float* wo      = (const float*)d_in[6];
    const float* bo      = (const float*)d_in[7];
    const float* w1      = (const float*)d_in[8];
    const float* b1      = (const float*)d_in[9];
    const float* w2      = (const float*)d_in[10];
    const float* b2      = (const float*)d_in[11];
    const float* g1      = (const float*)d_in[12];
    const float* be1     = (const float*)d_in[13];
    const float* g2      = (const float*)d_in[14];
    const float* be2     = (const float*)d_in[15];
    const float* wlm     = (const float*)d_in[16];
    const float* blm     = (const float*)d_in[17];
    float* out = (float*)d_out;

    float* px;
    __half *ph_h, *ph_l, *patt_h, *patt_l, *pff_h, *pff_l, *px_h;
    __half *pqkvh, *pqkvl;
    __half *pqkvT_h, *pqkvT_l, *pwoT_h, *pwoT_l, *pw1T_h, *pw1T_l,
           *pw2T_h, *pw2T_l, *plmT_h;
    cudaGetSymbolAddress((void**)&px,     g_x);
    cudaGetSymbolAddress((void**)&ph_h,   g_h_hi);
    cudaGetSymbolAddress((void**)&ph_l,   g_h_lo);
    cudaGetSymbolAddress((void**)&patt_h, g_att_hi);
    cudaGetSymbolAddress((void**)&patt_l, g_att_lo);
    cudaGetSymbolAddress((void**)&pff_h,  g_ff_hi);
    cudaGetSymbolAddress((void**)&pff_l,  g_ff_lo);
    cudaGetSymbolAddress((void**)&px_h,   g_x_hi);
    cudaGetSymbolAddress((void**)&pqkvh,  g_qkvh);
    cudaGetSymbolAddress((void**)&pqkvl,  g_qkvl);
    cudaGetSymbolAddress((void**)&pqkvT_h, g_wqkvT_hi);
    cudaGetSymbolAddress((void**)&pqkvT_l, g_wqkvT_lo);
    cudaGetSymbolAddress((void**)&pwoT_h,  g_woT_hi);
    cudaGetSymbolAddress((void**)&pwoT_l,  g_woT_lo);
    cudaGetSymbolAddress((void**)&pw1T_h,  g_w1T_hi);
    cudaGetSymbolAddress((void**)&pw1T_l,  g_w1T_lo);
    cudaGetSymbolAddress((void**)&pw2T_h,  g_w2T_hi);
    cudaGetSymbolAddress((void**)&pw2T_l,  g_w2T_lo);
    cudaGetSymbolAddress((void**)&plmT_h,  g_wlmT_hi);

    cudaFuncSetAttribute((const void*)gemm2_k<1, 1, 128>, cudaFuncAttributeMaxDynamicSharedMemorySize, GEMM_SMEM_128);
    cudaFuncSetAttribute((const void*)gemm2_k<2, 3, 128>, cudaFuncAttributeMaxDynamicSharedMemorySize, GEMM_SMEM_128);
    cudaFuncSetAttribute((const void*)gemm2_k<4, 3, 128>, cudaFuncAttributeMaxDynamicSharedMemorySize, GEMM_SMEM_128);
    cudaFuncSetAttribute((const void*)gemm2_k<3, 3, 64>,  cudaFuncAttributeMaxDynamicSharedMemorySize, GEMM_SMEM_64);
    cudaFuncSetAttribute((const void*)gemm2_k<7, 3, 64>,  cudaFuncAttributeMaxDynamicSharedMemorySize, GEMM_SMEM_64);
    cudaFuncSetAttribute(flash_attn_k, cudaFuncAttributeMaxDynamicSharedMemorySize, ATT_SMEM);

    {
        int total = LL * 3 * DD * DD;
        prep_qkvT_k<<<(total + 255) / 256, 256>>>(wq, wk, wv);
        dim3 blk(32, 8);
        tsplit_k<<<dim3(DD / 32, DD / 32, LL), blk>>>(wo, pwoT_h, pwoT_l, DD, DD);
        tsplit_k<<<dim3(FFD / 32, DD / 32, LL), blk>>>(w1, pw1T_h, pw1T_l, DD, FFD);
        tsplit_k<<<dim3(DD / 32, FFD / 32, LL), blk>>>(w2, pw2T_h, pw2T_l, FFD, DD);
        tsplit_hi_k<<<dim3(VV / 32, DD / 32, 1), blk>>>(wlm, plmT_h, DD, VV);
        embed_k<<<(MM * DD + 255) / 256, 256>>>(idx, tok_emb, pos_emb);
    }

    for (int l = 0; l < LL; l++) {
        layernorm_k<<<MM, 256>>>(px, g1 + l * DD, be1 + l * DD, ph_h, ph_l);
        gemm2_k<4, 3, 128><<<dim3(3 * DD / 128, MM / 128), 256, GEMM_SMEM_128>>>(
            MM, 3 * DD, DD, ph_h, ph_l,
            pqkvT_h + (size_t)l * 3 * DD * DD,
            pqkvT_l + (size_t)l * 3 * DD * DD,
            nullptr, nullptr, nullptr, pqkvh, pqkvl);
        flash_attn_k<<<dim3(16, 24), 128, ATT_SMEM>>>(pqkvh, pqkvl, patt_h, patt_l);
        gemm2_k<3, 3, 64><<<dim3(DD / 128, MM / 64), 128, GEMM_SMEM_64>>>(
            MM, DD, DD, patt_h, patt_l,
            pwoT_h + (size_t)l * DD * DD,
            pwoT_l + (size_t)l * DD * DD,
            bo + l * DD, px, px, nullptr, nullptr);
        layernorm_k<<<MM, 256>>>(px, g2 + l * DD, be2 + l * DD, ph_h, ph_l);
        gemm2_k<2, 3, 128><<<dim3(FFD / 128, MM / 128), 256, GEMM_SMEM_128>>>(
            MM, FFD, DD, ph_h, ph_l,
            pw1T_h + (size_t)l * FFD * DD,
            pw1T_l + (size_t)l * FFD * DD,
            b1 + l * FFD, nullptr, nullptr, pff_h, pff_l);
        if (l < LL - 1) {
            gemm2_k<3, 3, 64><<<dim3(DD / 128, MM / 64), 128, GEMM_SMEM_64>>>(
                MM, DD, FFD, pff_h, pff_l,
                pw2T_h + (size_t)l * DD * FFD,
                pw2T_l + (size_t)l * DD * FFD,
                b2 + l * DD, px, px, nullptr, nullptr);
        } else {
            // last layer: fp32 x store is dead; emit hi-split only
            gemm2_k<7, 3, 64><<<dim3(DD / 128, MM / 64), 128, GEMM_SMEM_64>>>(
                MM, DD, FFD, pff_h, pff_l,
                pw2T_h + (size_t)l * DD * FFD,
                pw2T_l + (size_t)l * DD * FFD,
                b2 + l * DD, px, nullptr, px_h, nullptr);
        }
    }

    // LM head (final op): 1-term fp16, streaming fp32 stores
    gemm2_k<1, 1, 128><<<dim3(VV / 128, MM / 128), 256, GEMM_SMEM_128>>>(
        MM, VV, DD, px_h, nullptr, plmT_h, nullptr, blm, nullptr, out,
        nullptr, nullptr);
}